// round 10
// baseline (speedup 1.0000x reference)
#include <cuda_runtime.h>
#include <cuda_fp16.h>
#include <cstdint>
#include <math.h>

#define S_LEN 2048
#define HID   2048
#define NHQ   16
#define NKV   4
#define HD    128
#define WIN   1024

// ---------------- scratch (no cudaMalloc allowed) ----------------
__device__ __half   g_hsh[S_LEN * HID];                // fp16 hidden state (A operand)
__device__ uint32_t g_qh[S_LEN * (NHQ * HD) / 2];      // fp16 q (rope applied), half2
__device__ uint32_t g_kh[S_LEN * (NKV * HD) / 2];      // fp16 k (rope applied), half2
__device__ uint32_t g_vh[S_LEN * (NKV * HD) / 2];      // fp16 v, half2
__device__ uint32_t g_attnh[S_LEN * (NHQ * HD) / 2];   // fp16 attention out, half2
__device__ uint32_t g_wqp[(HID / 2) * (NHQ * HD)];     // k-pair-packed fp16 weights
__device__ uint32_t g_wkp[(HID / 2) * (NKV * HD)];
__device__ uint32_t g_wvp[(HID / 2) * (NKV * HD)];
__device__ uint32_t g_wop[((NHQ * HD) / 2) * HID];

__device__ __forceinline__ uint32_t pack2(float a, float b) {
    __half2 h = __floats2half2_rn(a, b);
    return *reinterpret_cast<uint32_t*>(&h);
}
__device__ __forceinline__ void mma_h16(float c[4], const uint32_t a[4], const uint32_t b[2]) {
    asm volatile("mma.sync.aligned.m16n8k16.row.col.f32.f16.f16.f32 "
        "{%0,%1,%2,%3}, {%4,%5,%6,%7}, {%8,%9}, {%0,%1,%2,%3};"
        : "+f"(c[0]), "+f"(c[1]), "+f"(c[2]), "+f"(c[3])
        : "r"(a[0]), "r"(a[1]), "r"(a[2]), "r"(a[3]), "r"(b[0]), "r"(b[1]));
}
__device__ __forceinline__ void ldsm_x4(uint32_t r[4], uint32_t addr) {
    asm volatile("ldmatrix.sync.aligned.m8n8.x4.shared.b16 {%0,%1,%2,%3}, [%4];"
        : "=r"(r[0]), "=r"(r[1]), "=r"(r[2]), "=r"(r[3]) : "r"(addr));
}
__device__ __forceinline__ void ldsm_x4_t(uint32_t r[4], uint32_t addr) {
    asm volatile("ldmatrix.sync.aligned.m8n8.x4.trans.shared.b16 {%0,%1,%2,%3}, [%4];"
        : "=r"(r[0]), "=r"(r[1]), "=r"(r[2]), "=r"(r[3]) : "r"(addr));
}
__device__ __forceinline__ uint32_t smem_u32(const void* p) {
    uint32_t a;
    asm("{ .reg .u64 t; cvta.to.shared.u64 t, %1; cvt.u32.u64 %0, t; }" : "=r"(a) : "l"(p));
    return a;
}
__device__ __forceinline__ void cp16(uint32_t s, const void* g) {
    asm volatile("cp.async.ca.shared.global [%0], [%1], 16;" :: "r"(s), "l"(g));
}
#define CP_COMMIT() asm volatile("cp.async.commit_group;" ::: "memory")
#define CP_WAIT1()  asm volatile("cp.async.wait_group 1;" ::: "memory")

// ---------------------------------------------------------------------------
// fp32 -> fp16 convert of hidden state; 8 elems/thread
// ---------------------------------------------------------------------------
__global__ void conv_half(const float* __restrict__ src, __half* __restrict__ dst) {
    int i = (blockIdx.x * blockDim.x + threadIdx.x) * 8;
    float4 v0 = *reinterpret_cast<const float4*>(src + i);
    float4 v1 = *reinterpret_cast<const float4*>(src + i + 4);
    uint4 o = { pack2(v0.x, v0.y), pack2(v0.z, v0.w), pack2(v1.x, v1.y), pack2(v1.z, v1.w) };
    *reinterpret_cast<uint4*>(dst + i) = o;
}

// ---------------------------------------------------------------------------
// pack all 4 weights in one launch: W[K][N] fp32 -> Wp[K/2][N] half2 pairs.
// ---------------------------------------------------------------------------
#define SEG_Q ((HID / 2) * (NHQ * HD) / 4)
#define SEG_K ((HID / 2) * (NKV * HD) / 4)
#define SEG_O (((NHQ * HD) / 2) * HID / 4)

__global__ void pack_all(const float* __restrict__ Wq, const float* __restrict__ Wk,
                         const float* __restrict__ Wv, const float* __restrict__ Wo) {
    int u = blockIdx.x * blockDim.x + threadIdx.x;
    const float* W; uint32_t* Wp; int N;
    if (u < SEG_Q)                     { W = Wq; Wp = g_wqp; N = NHQ * HD; }
    else if (u < SEG_Q + SEG_K)        { W = Wk; Wp = g_wkp; N = NKV * HD; u -= SEG_Q; }
    else if (u < SEG_Q + 2 * SEG_K)    { W = Wv; Wp = g_wvp; N = NKV * HD; u -= SEG_Q + SEG_K; }
    else                               { W = Wo; Wp = g_wop; N = HID;      u -= SEG_Q + 2 * SEG_K; }
    int nc4 = N >> 2;
    int r2 = u / nc4, c = (u % nc4) * 4;
    float4 a = *reinterpret_cast<const float4*>(&W[(size_t)(2 * r2) * N + c]);
    float4 b = *reinterpret_cast<const float4*>(&W[(size_t)(2 * r2 + 1) * N + c]);
    uint4 o = { pack2(a.x, b.x), pack2(a.y, b.y), pack2(a.z, b.z), pack2(a.w, b.w) };
    *reinterpret_cast<uint4*>(&Wp[(size_t)r2 * N + c]) = o;
}

// ---------------------------------------------------------------------------
// fp16 cp.async GEMM, CTA tile 128 x (NI*32), 8 warps (2x4), warp 64 x (NI*8),
// K-tile 32, 3 stages. A fragments via ldmatrix.x4.
// EPI==0: fp32 output (O projection, NI=8). EPI==1: fused QKV + RoPE (NI=4).
// ---------------------------------------------------------------------------
#define AS2 20
#define A_U32 (128 * AS2)

template<int NI, int EPI>
__global__ __launch_bounds__(256, 1) void gemm_h(const __half* __restrict__ Ah, int K,
                                                 const uint32_t* __restrict__ Wp0, int nb0,
                                                 const uint32_t* __restrict__ Wp1, int nb1,
                                                 const uint32_t* __restrict__ Wp2,
                                                 float* __restrict__ Cout,
                                                 const float* __restrict__ fc,
                                                 const int* __restrict__ pos) {
    constexpr int TN  = NI * 32;
    constexpr int BS2 = TN + 8;
    constexpr int B_U32 = 16 * BS2;
    constexpr int STG = A_U32 + B_U32;
    constexpr int BCP = TN / 64;

    extern __shared__ uint32_t smg[];
    const uint32_t sbase = smem_u32(smg);

    const int tid  = threadIdx.x;
    const int lane = tid & 31;
    const int wid  = tid >> 5;
    const int wm   = wid & 1;
    const int wn   = wid >> 1;
    const int g    = lane >> 2;
    const int tig  = lane & 3;
    const int brow = blockIdx.y * 128;

    // ldmatrix lane geometry for A fragments
    const int arow = (lane & 7) + ((lane & 8) ? 8 : 0);
    const int acsel = (lane & 16) ? 4 : 0;

    const uint32_t* Wp; int N, cloc, dest = 0;
    {
        int bx = blockIdx.x;
        if (bx < nb0)            { Wp = Wp0; N = (EPI ? NHQ * HD : HID); cloc = bx * TN; dest = 0; }
        else if (bx < nb0 + nb1) { Wp = Wp1; N = NKV * HD; cloc = (bx - nb0) * TN; dest = 1; }
        else                     { Wp = Wp2; N = NKV * HD; cloc = (bx - nb0 - nb1) * TN; dest = 2; }
    }

    float acc[4][NI][4];
#pragma unroll
    for (int mi = 0; mi < 4; ++mi)
#pragma unroll
        for (int ni = 0; ni < NI; ++ni)
#pragma unroll
            for (int f = 0; f < 4; ++f) acc[mi][ni][f] = 0.f;

    const int iters = K / 32;

#define ISSUE_STAGE(st, k0)                                                          \
    do {                                                                             \
        uint32_t soff = sbase + (uint32_t)((st) * STG) * 4u;                         \
        _Pragma("unroll")                                                            \
        for (int i = 0; i < 2; ++i) {                                                \
            int idx = tid + i * 256;                                                 \
            int r = idx >> 2, ch = idx & 3;                                          \
            cp16(soff + (uint32_t)(r * AS2 * 4 + ch * 16),                           \
                 &Ah[(size_t)(brow + r) * K + (k0) + ch * 8]);                       \
        }                                                                            \
        _Pragma("unroll")                                                            \
        for (int i = 0; i < BCP; ++i) {                                              \
            int idx = tid + i * 256;                                                 \
            int r = idx / (TN / 4), ch = idx % (TN / 4);                             \
            cp16(soff + (uint32_t)(A_U32 * 4 + r * BS2 * 4 + ch * 16),               \
                 &Wp[(size_t)((k0) / 2 + r) * N + cloc + ch * 4]);                   \
        }                                                                            \
        CP_COMMIT();                                                                 \
    } while (0)

    ISSUE_STAGE(0, 0);
    ISSUE_STAGE(1, 32);

    for (int kt = 0; kt < iters; ++kt) {
        CP_WAIT1();
        __syncthreads();

        if (kt + 2 < iters) {
            ISSUE_STAGE((kt + 2) % 3, (kt + 2) * 32);
        } else {
            CP_COMMIT();
        }

        const uint32_t stg_base = sbase + (uint32_t)((kt % 3) * STG) * 4u;
        const uint32_t* Bs = smg + (kt % 3) * STG + A_U32;

#pragma unroll
        for (int kk = 0; kk < 2; ++kk) {
            const int kb2 = kk * 8;
            uint32_t af[4][4], bf[NI][2];
#pragma unroll
            for (int mi = 0; mi < 4; ++mi) {
                int r0 = wm * 64 + mi * 16 + arow;
                ldsm_x4(af[mi], stg_base + (uint32_t)(r0 * AS2 + kb2 + acsel) * 4u);
            }
#pragma unroll
            for (int ni = 0; ni < NI; ++ni) {
                int c0 = wn * (NI * 8) + ni * 8 + g;
                bf[ni][0] = Bs[(kb2 + tig) * BS2 + c0];
                bf[ni][1] = Bs[(kb2 + tig + 4) * BS2 + c0];
            }
#pragma unroll
            for (int mi = 0; mi < 4; ++mi)
#pragma unroll
                for (int ni = 0; ni < NI; ++ni)
                    mma_h16(acc[mi][ni], af[mi], bf[ni]);
        }
        __syncthreads();
    }
#undef ISSUE_STAGE

    if (EPI == 0) {
#pragma unroll
        for (int mi = 0; mi < 4; ++mi) {
            int r0 = brow + wm * 64 + mi * 16 + g;
#pragma unroll
            for (int ni = 0; ni < NI; ++ni) {
                int c0 = cloc + wn * (NI * 8) + ni * 8 + 2 * tig;
                float2 v0 = make_float2(acc[mi][ni][0], acc[mi][ni][1]);
                float2 v1 = make_float2(acc[mi][ni][2], acc[mi][ni][3]);
                *reinterpret_cast<float2*>(&Cout[(size_t)r0 * N + c0])       = v0;
                *reinterpret_cast<float2*>(&Cout[(size_t)(r0 + 8) * N + c0]) = v1;
            }
        }
    } else {
        uint32_t* dst = (dest == 0) ? g_qh : (dest == 1) ? g_kh : g_vh;
        const int rstr = (dest == 0) ? (NHQ * HD / 2) : (NKV * HD / 2);
#pragma unroll
        for (int mi = 0; mi < 4; ++mi) {
            int r0 = brow + wm * 64 + mi * 16 + g;
            int r1 = r0 + 8;
            int p0 = pos[r0], p1 = pos[r1];
#pragma unroll
            for (int ni = 0; ni < NI; ++ni) {
                int c0 = cloc + wn * (NI * 8) + ni * 8 + 2 * tig;
                float a0 = acc[mi][ni][0], b0 = acc[mi][ni][1];
                float a1 = acc[mi][ni][2], b1 = acc[mi][ni][3];
                if (dest < 2) {
                    int dcol = c0 & (HD - 1);
                    float2 cs0 = *reinterpret_cast<const float2*>(&fc[(size_t)p0 * HD + dcol]);
                    float2 cs1 = *reinterpret_cast<const float2*>(&fc[(size_t)p1 * HD + dcol]);
                    float na0 = a0 * cs0.x - b0 * cs0.y;
                    float nb0 = a0 * cs0.y + b0 * cs0.x;
                    float na1 = a1 * cs1.x - b1 * cs1.y;
                    float nb1 = a1 * cs1.y + b1 * cs1.x;
                    a0 = na0; b0 = nb0; a1 = na1; b1 = nb1;
                }
                dst[(size_t)r0 * rstr + (c0 >> 1)] = pack2(a0, b0);
                dst[(size_t)r1 * rstr + (c0 >> 1)] = pack2(a1, b1);
            }
        }
    }
}

// ---------------------------------------------------------------------------
// Flash attention, fp16 m16n8k16, cp.async double-buffered K/V,
// ldmatrix fragments (V via .trans from raw tile — no repack).
// smem (u32): Q[128*68] | K0[64*68] K1 | V0[64*68] V1 | P[128*36]
// ---------------------------------------------------------------------------
#define QS2 68
#define KVS 68
#define PS2 36
#define KV_TILE (64 * KVS)
#define PS_OFF (128 * QS2 + 4 * KV_TILE)
#define ATT_SMEM ((PS_OFF + 128 * PS2) * 4)

__global__ __launch_bounds__(256, 1) void attn_h(uint32_t* __restrict__ outh) {
    extern __shared__ uint32_t smu[];
    const uint32_t sbase = smem_u32(smu);
    const uint32_t kvbase = sbase + (uint32_t)(128 * QS2) * 4u;
    uint32_t* Ps = smu + PS_OFF;

    const int q0  = blockIdx.x * 128;
    const int h   = blockIdx.y;
    const int kvh = h >> 2;
    const int tid = threadIdx.x;
    const int lane = tid & 31;
    const int wq  = tid >> 5;
    const int g   = lane >> 2;
    const int tig = lane & 3;
    const int rb  = wq * 16;

    // ldmatrix lane geometry
    const int arow  = (lane & 7) + ((lane & 8) ? 8 : 0);   // A-frag / V-row local
    const int acsel = (lane & 16) ? 4 : 0;                 // A-frag k-col select
    const int krow  = (lane & 7) + ((lane & 16) ? 8 : 0);  // K-bfrag row local (within nf pair)
    const int kcsel = (lane & 8) ? 4 : 0;                  // K-bfrag k-col select
    const int vcsel = (lane & 16) ? 1 : 0;                 // V-bfrag nf select

    const float scale = 0.08838834764831845f;
    const float NEG = -1e30f, GUARD = -1e29f;

    // Q tile: raw u32 copy (already fp16)
#pragma unroll
    for (int i = 0; i < 8; ++i) {
        int idx = i * 256 + tid;
        int r = idx >> 4, j4 = (idx & 15) * 4;
        uint4 v = *reinterpret_cast<const uint4*>(&g_qh[(size_t)(q0 + r) * (NHQ * HD / 2) + h * (HD / 2) + j4]);
        *reinterpret_cast<uint4*>(&smu[r * QS2 + j4]) = v;
    }

    float m0 = NEG, m1 = NEG, l0 = 0.f, l1 = 0.f;
    float o[16][4];
#pragma unroll
    for (int nf = 0; nf < 16; ++nf)
#pragma unroll
        for (int f = 0; f < 4; ++f) o[nf][f] = 0.f;

    int lo = q0 - (WIN - 1); if (lo < 0) lo = 0;
    const int kb_lo = lo >> 6;
    const int kb_hi = (q0 + 127) >> 6;

    const uint32_t qfrag = sbase + (uint32_t)((rb + arow) * QS2 + acsel) * 4u;
    const uint32_t pfrag = sbase + (uint32_t)(PS_OFF + (rb + arow) * PS2 + acsel) * 4u;

#define AISSUE(t0_, buf_)                                                             \
    do {                                                                              \
        uint32_t kb_ = kvbase + (uint32_t)((buf_) * KV_TILE) * 4u;                    \
        uint32_t vb_ = kvbase + (uint32_t)((2 + (buf_)) * KV_TILE) * 4u;              \
        _Pragma("unroll")                                                             \
        for (int i = 0; i < 4; ++i) {                                                 \
            int idx = tid + i * 256;                                                  \
            int r = idx >> 4, c = (idx & 15) * 4;                                     \
            cp16(kb_ + (uint32_t)(r * KVS + c) * 4u,                                  \
                 &g_kh[(size_t)((t0_) + r) * (NKV * HD / 2) + kvh * (HD / 2) + c]);   \
        }                                                                             \
        _Pragma("unroll")                                                             \
        for (int i = 0; i < 4; ++i) {                                                 \
            int idx = tid + i * 256;                                                  \
            int r = idx >> 4, c = (idx & 15) * 4;                                     \
            cp16(vb_ + (uint32_t)(r * KVS + c) * 4u,                                  \
                 &g_vh[(size_t)((t0_) + r) * (NKV * HD / 2) + kvh * (HD / 2) + c]);   \
        }                                                                             \
        CP_COMMIT();                                                                  \
    } while (0)

    AISSUE(kb_lo * 64, 0);

    for (int kb = kb_lo; kb <= kb_hi; ++kb) {
        const int t0 = kb * 64;
        const int buf = (kb - kb_lo) & 1;
        if (kb < kb_hi) AISSUE((kb + 1) * 64, buf ^ 1);
        else            CP_COMMIT();
        CP_WAIT1();
        __syncthreads();

        const uint32_t kbuf = kvbase + (uint32_t)(buf * KV_TILE) * 4u;
        const uint32_t vbuf = kvbase + (uint32_t)((2 + buf) * KV_TILE) * 4u;

        // ---- S = Q @ K^T ----
        float s[8][4];
#pragma unroll
        for (int nf = 0; nf < 8; ++nf)
#pragma unroll
            for (int f = 0; f < 4; ++f) s[nf][f] = 0.f;

#pragma unroll
        for (int ks = 0; ks < 8; ++ks) {
            uint32_t a[4];
            ldsm_x4(a, qfrag + (uint32_t)(ks * 8) * 4u);
#pragma unroll
            for (int nf = 0; nf < 8; nf += 2) {
                uint32_t b[4];
                ldsm_x4(b, kbuf + (uint32_t)((nf * 8 + krow) * KVS + ks * 8 + kcsel) * 4u);
                mma_h16(s[nf],     a, b);
                mma_h16(s[nf + 1], a, b + 2);
            }
        }

        // ---- mask + scale ----
        const int r0g = q0 + rb + g, r1g = r0g + 8;
#pragma unroll
        for (int nf = 0; nf < 8; ++nf) {
            int c0 = t0 + nf * 8 + 2 * tig;
            int c1 = c0 + 1;
            bool ok00 = (c0 <= r0g) && (r0g - c0 < WIN);
            bool ok01 = (c1 <= r0g) && (r0g - c1 < WIN);
            bool ok10 = (c0 <= r1g) && (r1g - c0 < WIN);
            bool ok11 = (c1 <= r1g) && (r1g - c1 < WIN);
            s[nf][0] = ok00 ? s[nf][0] * scale : NEG;
            s[nf][1] = ok01 ? s[nf][1] * scale : NEG;
            s[nf][2] = ok10 ? s[nf][2] * scale : NEG;
            s[nf][3] = ok11 ? s[nf][3] * scale : NEG;
        }

        // ---- online softmax ----
        float mt0 = NEG, mt1 = NEG;
#pragma unroll
        for (int nf = 0; nf < 8; ++nf) {
            mt0 = fmaxf(mt0, fmaxf(s[nf][0], s[nf][1]));
            mt1 = fmaxf(mt1, fmaxf(s[nf][2], s[nf][3]));
        }
        mt0 = fmaxf(mt0, __shfl_xor_sync(0xffffffffu, mt0, 1));
        mt0 = fmaxf(mt0, __shfl_xor_sync(0xffffffffu, mt0, 2));
        mt1 = fmaxf(mt1, __shfl_xor_sync(0xffffffffu, mt1, 1));
        mt1 = fmaxf(mt1, __shfl_xor_sync(0xffffffffu, mt1, 2));

        float mn0 = fmaxf(m0, mt0), mn1 = fmaxf(m1, mt1);
        float esc0 = (m0 > GUARD) ? __expf(m0 - mn0) : 0.f;
        float esc1 = (m1 > GUARD) ? __expf(m1 - mn1) : 0.f;

        float rs0 = 0.f, rs1 = 0.f;
#pragma unroll
        for (int nf = 0; nf < 8; ++nf) {
            float p00 = (s[nf][0] > GUARD) ? __expf(s[nf][0] - mn0) : 0.f;
            float p01 = (s[nf][1] > GUARD) ? __expf(s[nf][1] - mn0) : 0.f;
            float p10 = (s[nf][2] > GUARD) ? __expf(s[nf][2] - mn1) : 0.f;
            float p11 = (s[nf][3] > GUARD) ? __expf(s[nf][3] - mn1) : 0.f;
            rs0 += p00 + p01;
            rs1 += p10 + p11;
            Ps[(rb + g) * PS2 + nf * 4 + tig]     = pack2(p00, p01);
            Ps[(rb + g + 8) * PS2 + nf * 4 + tig] = pack2(p10, p11);
        }
        rs0 += __shfl_xor_sync(0xffffffffu, rs0, 1);
        rs0 += __shfl_xor_sync(0xffffffffu, rs0, 2);
        rs1 += __shfl_xor_sync(0xffffffffu, rs1, 1);
        rs1 += __shfl_xor_sync(0xffffffffu, rs1, 2);

        l0 = l0 * esc0 + rs0; m0 = mn0;
        l1 = l1 * esc1 + rs1; m1 = mn1;

#pragma unroll
        for (int nf = 0; nf < 16; ++nf) {
            o[nf][0] *= esc0; o[nf][1] *= esc0;
            o[nf][2] *= esc1; o[nf][3] *= esc1;
        }
        __syncwarp(0xffffffffu);   // Ps rows are warp-private

        // ---- O += P @ V (V fragments via ldmatrix.trans on raw tile) ----
#pragma unroll
        for (int ks = 0; ks < 4; ++ks) {
            uint32_t a[4];
            ldsm_x4(a, pfrag + (uint32_t)(ks * 8) * 4u);
#pragma unroll
            for (int nf = 0; nf < 16; nf += 2) {
                uint32_t b[4];
                ldsm_x4_t(b, vbuf + (uint32_t)((ks * 16 + arow) * KVS + (nf + vcsel) * 4) * 4u);
                mma_h16(o[nf],     a, b);
                mma_h16(o[nf + 1], a, b + 2);
            }
        }
        __syncthreads();   // all warps done with buf before it is re-issued
    }
#undef AISSUE

    // ---- epilogue: fp16 half2 output ----
    const float inv0 = 1.f / l0, inv1 = 1.f / l1;
    const int qr0 = q0 + rb + g, qr1 = qr0 + 8;
#pragma unroll
    for (int nf = 0; nf < 16; ++nf) {
        int c2 = h * (HD / 2) + nf * 4 + tig;
        outh[(size_t)qr0 * (NHQ * HD / 2) + c2] = pack2(o[nf][0] * inv0, o[nf][1] * inv0);
        outh[(size_t)qr1 * (NHQ * HD / 2) + c2] = pack2(o[nf][2] * inv1, o[nf][3] * inv1);
    }
}

// ---------------------------------------------------------------------------
extern "C" void kernel_launch(void* const* d_in, const int* in_sizes, int n_in,
                              void* d_out, int out_size) {
    const float* hs  = (const float*)d_in[0];
    const float* fc  = (const float*)d_in[1];
    const int*   pos = (const int*)d_in[4];
    const float* Wq  = (const float*)d_in[5];
    const float* Wk  = (const float*)d_in[6];
    const float* Wv  = (const float*)d_in[7];
    const float* Wo  = (const float*)d_in[8];
    float* out = (float*)d_out;

    __half *hsh;
    uint32_t *attnh, *wqp, *wkp, *wvp, *wop;
    cudaGetSymbolAddress((void**)&hsh,   g_hsh);
    cudaGetSymbolAddress((void**)&attnh, g_attnh);
    cudaGetSymbolAddress((void**)&wqp,   g_wqp);
    cudaGetSymbolAddress((void**)&wkp,   g_wkp);
    cudaGetSymbolAddress((void**)&wvp,   g_wvp);
    cudaGetSymbolAddress((void**)&wop,   g_wop);

    conv_half<<<(S_LEN * HID) / (256 * 8), 256>>>(hs, hsh);
    pack_all<<<(SEG_Q + 2 * SEG_K + SEG_O) / 256, 256>>>(Wq, Wk, Wv, Wo);

    constexpr int SMEM_QKV = 3 * (A_U32 + 16 * (128 + 8)) * 4;
    constexpr int SMEM_O   = 3 * (A_U32 + 16 * (256 + 8)) * 4;
    cudaFuncSetAttribute((const void*)gemm_h<4, 1>, cudaFuncAttributeMaxDynamicSharedMemorySize, SMEM_QKV);
    cudaFuncSetAttribute((const void*)gemm_h<8, 0>, cudaFuncAttributeMaxDynamicSharedMemorySize, SMEM_O);
    cudaFuncSetAttribute((const void*)attn_h, cudaFuncAttributeMaxDynamicSharedMemorySize, ATT_SMEM);

    // fused QKV + RoPE: 128x128 tiles, 24 col blocks (16 Q + 4 K + 4 V) x 16 rows
    gemm_h<4, 1><<<dim3(24, 16), 256, SMEM_QKV>>>(hsh, HID, wqp, 16, wkp, 4, wvp,
                                                  nullptr, fc, pos);

    // attention: grid (qblock, head) for light/heavy wave mixing
    attn_h<<<dim3(S_LEN / 128, NHQ), 256, ATT_SMEM>>>(attnh);

    // O projection: 128x256 tiles, 8x16 = 128 CTAs
    gemm_h<8, 0><<<dim3(8, 16), 256, SMEM_O>>>((const __half*)attnh, NHQ * HD, wop, 8,
                                               nullptr, 0, nullptr, out, nullptr, nullptr);
}

// round 11
// speedup vs baseline: 1.0198x; 1.0198x over previous
#include <cuda_runtime.h>
#include <cuda_fp16.h>
#include <cstdint>
#include <math.h>

#define S_LEN 2048
#define HID   2048
#define NHQ   16
#define NKV   4
#define HD    128
#define WIN   1024

// ---------------- scratch (no cudaMalloc allowed) ----------------
__device__ __half   g_hsh[S_LEN * HID];
__device__ uint32_t g_qh[S_LEN * (NHQ * HD) / 2];
__device__ uint32_t g_kh[S_LEN * (NKV * HD) / 2];
__device__ uint32_t g_vh[S_LEN * (NKV * HD) / 2];
__device__ uint32_t g_attnh[S_LEN * (NHQ * HD) / 2];
__device__ uint32_t g_wqp[(HID / 2) * (NHQ * HD)];
__device__ uint32_t g_wkp[(HID / 2) * (NKV * HD)];
__device__ uint32_t g_wvp[(HID / 2) * (NKV * HD)];
__device__ uint32_t g_wop[((NHQ * HD) / 2) * HID];

__device__ __forceinline__ uint32_t pack2(float a, float b) {
    __half2 h = __floats2half2_rn(a, b);
    return *reinterpret_cast<uint32_t*>(&h);
}
__device__ __forceinline__ void mma_h16(float c[4], const uint32_t a[4], const uint32_t b[2]) {
    asm volatile("mma.sync.aligned.m16n8k16.row.col.f32.f16.f16.f32 "
        "{%0,%1,%2,%3}, {%4,%5,%6,%7}, {%8,%9}, {%0,%1,%2,%3};"
        : "+f"(c[0]), "+f"(c[1]), "+f"(c[2]), "+f"(c[3])
        : "r"(a[0]), "r"(a[1]), "r"(a[2]), "r"(a[3]), "r"(b[0]), "r"(b[1]));
}
__device__ __forceinline__ void ldsm_x4(uint32_t r[4], uint32_t addr) {
    asm volatile("ldmatrix.sync.aligned.m8n8.x4.shared.b16 {%0,%1,%2,%3}, [%4];"
        : "=r"(r[0]), "=r"(r[1]), "=r"(r[2]), "=r"(r[3]) : "r"(addr));
}
__device__ __forceinline__ void ldsm_x4_t(uint32_t r[4], uint32_t addr) {
    asm volatile("ldmatrix.sync.aligned.m8n8.x4.trans.shared.b16 {%0,%1,%2,%3}, [%4];"
        : "=r"(r[0]), "=r"(r[1]), "=r"(r[2]), "=r"(r[3]) : "r"(addr));
}
__device__ __forceinline__ uint32_t smem_u32(const void* p) {
    uint32_t a;
    asm("{ .reg .u64 t; cvta.to.shared.u64 t, %1; cvt.u32.u64 %0, t; }" : "=r"(a) : "l"(p));
    return a;
}
__device__ __forceinline__ void cp16(uint32_t s, const void* g) {
    asm volatile("cp.async.ca.shared.global [%0], [%1], 16;" :: "r"(s), "l"(g));
}
#define CP_COMMIT() asm volatile("cp.async.commit_group;" ::: "memory")
#define CP_WAIT1()  asm volatile("cp.async.wait_group 1;" ::: "memory")

// ---------------------------------------------------------------------------
__global__ void conv_half(const float* __restrict__ src, __half* __restrict__ dst) {
    int i = (blockIdx.x * blockDim.x + threadIdx.x) * 8;
    float4 v0 = *reinterpret_cast<const float4*>(src + i);
    float4 v1 = *reinterpret_cast<const float4*>(src + i + 4);
    uint4 o = { pack2(v0.x, v0.y), pack2(v0.z, v0.w), pack2(v1.x, v1.y), pack2(v1.z, v1.w) };
    *reinterpret_cast<uint4*>(dst + i) = o;
}

#define SEG_Q ((HID / 2) * (NHQ * HD) / 4)
#define SEG_K ((HID / 2) * (NKV * HD) / 4)
#define SEG_O (((NHQ * HD) / 2) * HID / 4)

__global__ void pack_all(const float* __restrict__ Wq, const float* __restrict__ Wk,
                         const float* __restrict__ Wv, const float* __restrict__ Wo) {
    int u = blockIdx.x * blockDim.x + threadIdx.x;
    const float* W; uint32_t* Wp; int N;
    if (u < SEG_Q)                     { W = Wq; Wp = g_wqp; N = NHQ * HD; }
    else if (u < SEG_Q + SEG_K)        { W = Wk; Wp = g_wkp; N = NKV * HD; u -= SEG_Q; }
    else if (u < SEG_Q + 2 * SEG_K)    { W = Wv; Wp = g_wvp; N = NKV * HD; u -= SEG_Q + SEG_K; }
    else                               { W = Wo; Wp = g_wop; N = HID;      u -= SEG_Q + 2 * SEG_K; }
    int nc4 = N >> 2;
    int r2 = u / nc4, c = (u % nc4) * 4;
    float4 a = *reinterpret_cast<const float4*>(&W[(size_t)(2 * r2) * N + c]);
    float4 b = *reinterpret_cast<const float4*>(&W[(size_t)(2 * r2 + 1) * N + c]);
    uint4 o = { pack2(a.x, b.x), pack2(a.y, b.y), pack2(a.z, b.z), pack2(a.w, b.w) };
    *reinterpret_cast<uint4*>(&Wp[(size_t)r2 * N + c]) = o;
}

// ---------------------------------------------------------------------------
// fp16 cp.async GEMM (unchanged from R10).
// ---------------------------------------------------------------------------
#define AS2 20
#define A_U32 (128 * AS2)

template<int NI, int EPI>
__global__ __launch_bounds__(256, 1) void gemm_h(const __half* __restrict__ Ah, int K,
                                                 const uint32_t* __restrict__ Wp0, int nb0,
                                                 const uint32_t* __restrict__ Wp1, int nb1,
                                                 const uint32_t* __restrict__ Wp2,
                                                 float* __restrict__ Cout,
                                                 const float* __restrict__ fc,
                                                 const int* __restrict__ pos) {
    constexpr int TN  = NI * 32;
    constexpr int BS2 = TN + 8;
    constexpr int B_U32 = 16 * BS2;
    constexpr int STG = A_U32 + B_U32;
    constexpr int BCP = TN / 64;

    extern __shared__ uint32_t smg[];
    const uint32_t sbase = smem_u32(smg);

    const int tid  = threadIdx.x;
    const int lane = tid & 31;
    const int wid  = tid >> 5;
    const int wm   = wid & 1;
    const int wn   = wid >> 1;
    const int g    = lane >> 2;
    const int tig  = lane & 3;
    const int brow = blockIdx.y * 128;

    const int arow = (lane & 7) + ((lane & 8) ? 8 : 0);
    const int acsel = (lane & 16) ? 4 : 0;

    const uint32_t* Wp; int N, cloc, dest = 0;
    {
        int bx = blockIdx.x;
        if (bx < nb0)            { Wp = Wp0; N = (EPI ? NHQ * HD : HID); cloc = bx * TN; dest = 0; }
        else if (bx < nb0 + nb1) { Wp = Wp1; N = NKV * HD; cloc = (bx - nb0) * TN; dest = 1; }
        else                     { Wp = Wp2; N = NKV * HD; cloc = (bx - nb0 - nb1) * TN; dest = 2; }
    }

    float acc[4][NI][4];
#pragma unroll
    for (int mi = 0; mi < 4; ++mi)
#pragma unroll
        for (int ni = 0; ni < NI; ++ni)
#pragma unroll
            for (int f = 0; f < 4; ++f) acc[mi][ni][f] = 0.f;

    const int iters = K / 32;

#define ISSUE_STAGE(st, k0)                                                          \
    do {                                                                             \
        uint32_t soff = sbase + (uint32_t)((st) * STG) * 4u;                         \
        _Pragma("unroll")                                                            \
        for (int i = 0; i < 2; ++i) {                                                \
            int idx = tid + i * 256;                                                 \
            int r = idx >> 2, ch = idx & 3;                                          \
            cp16(soff + (uint32_t)(r * AS2 * 4 + ch * 16),                           \
                 &Ah[(size_t)(brow + r) * K + (k0) + ch * 8]);                       \
        }                                                                            \
        _Pragma("unroll")                                                            \
        for (int i = 0; i < BCP; ++i) {                                              \
            int idx = tid + i * 256;                                                 \
            int r = idx / (TN / 4), ch = idx % (TN / 4);                             \
            cp16(soff + (uint32_t)(A_U32 * 4 + r * BS2 * 4 + ch * 16),               \
                 &Wp[(size_t)((k0) / 2 + r) * N + cloc + ch * 4]);                   \
        }                                                                            \
        CP_COMMIT();                                                                 \
    } while (0)

    ISSUE_STAGE(0, 0);
    ISSUE_STAGE(1, 32);

    for (int kt = 0; kt < iters; ++kt) {
        CP_WAIT1();
        __syncthreads();

        if (kt + 2 < iters) {
            ISSUE_STAGE((kt + 2) % 3, (kt + 2) * 32);
        } else {
            CP_COMMIT();
        }

        const uint32_t stg_base = sbase + (uint32_t)((kt % 3) * STG) * 4u;
        const uint32_t* Bs = smg + (kt % 3) * STG + A_U32;

#pragma unroll
        for (int kk = 0; kk < 2; ++kk) {
            const int kb2 = kk * 8;
            uint32_t af[4][4], bf[NI][2];
#pragma unroll
            for (int mi = 0; mi < 4; ++mi) {
                int r0 = wm * 64 + mi * 16 + arow;
                ldsm_x4(af[mi], stg_base + (uint32_t)(r0 * AS2 + kb2 + acsel) * 4u);
            }
#pragma unroll
            for (int ni = 0; ni < NI; ++ni) {
                int c0 = wn * (NI * 8) + ni * 8 + g;
                bf[ni][0] = Bs[(kb2 + tig) * BS2 + c0];
                bf[ni][1] = Bs[(kb2 + tig + 4) * BS2 + c0];
            }
#pragma unroll
            for (int mi = 0; mi < 4; ++mi)
#pragma unroll
                for (int ni = 0; ni < NI; ++ni)
                    mma_h16(acc[mi][ni], af[mi], bf[ni]);
        }
        __syncthreads();
    }
#undef ISSUE_STAGE

    if (EPI == 0) {
#pragma unroll
        for (int mi = 0; mi < 4; ++mi) {
            int r0 = brow + wm * 64 + mi * 16 + g;
#pragma unroll
            for (int ni = 0; ni < NI; ++ni) {
                int c0 = cloc + wn * (NI * 8) + ni * 8 + 2 * tig;
                float2 v0 = make_float2(acc[mi][ni][0], acc[mi][ni][1]);
                float2 v1 = make_float2(acc[mi][ni][2], acc[mi][ni][3]);
                *reinterpret_cast<float2*>(&Cout[(size_t)r0 * N + c0])       = v0;
                *reinterpret_cast<float2*>(&Cout[(size_t)(r0 + 8) * N + c0]) = v1;
            }
        }
    } else {
        uint32_t* dst = (dest == 0) ? g_qh : (dest == 1) ? g_kh : g_vh;
        const int rstr = (dest == 0) ? (NHQ * HD / 2) : (NKV * HD / 2);
#pragma unroll
        for (int mi = 0; mi < 4; ++mi) {
            int r0 = brow + wm * 64 + mi * 16 + g;
            int r1 = r0 + 8;
            int p0 = pos[r0], p1 = pos[r1];
#pragma unroll
            for (int ni = 0; ni < NI; ++ni) {
                int c0 = cloc + wn * (NI * 8) + ni * 8 + 2 * tig;
                float a0 = acc[mi][ni][0], b0 = acc[mi][ni][1];
                float a1 = acc[mi][ni][2], b1 = acc[mi][ni][3];
                if (dest < 2) {
                    int dcol = c0 & (HD - 1);
                    float2 cs0 = *reinterpret_cast<const float2*>(&fc[(size_t)p0 * HD + dcol]);
                    float2 cs1 = *reinterpret_cast<const float2*>(&fc[(size_t)p1 * HD + dcol]);
                    float na0 = a0 * cs0.x - b0 * cs0.y;
                    float nb0 = a0 * cs0.y + b0 * cs0.x;
                    float na1 = a1 * cs1.x - b1 * cs1.y;
                    float nb1 = a1 * cs1.y + b1 * cs1.x;
                    a0 = na0; b0 = nb0; a1 = na1; b1 = nb1;
                }
                dst[(size_t)r0 * rstr + (c0 >> 1)] = pack2(a0, b0);
                dst[(size_t)r1 * rstr + (c0 >> 1)] = pack2(a1, b1);
            }
        }
    }
}

// ---------------------------------------------------------------------------
// Flash attention: 64 q-rows/CTA, 4 warps, 2 CTAs per SM.
// Q pre-scaled by scale*log2e at load; softmax in exp2 domain.
// smem (u32): Q[64*68] | K0 K1 V0 V1 [64*68 each] | P[64*36]  = 94 KB
// ---------------------------------------------------------------------------
#define QS2 68
#define KVS 68
#define PS2 36
#define KV_TILE (64 * KVS)
#define PS_OFF (64 * QS2 + 4 * KV_TILE)
#define ATT_SMEM ((PS_OFF + 64 * PS2) * 4)

__global__ __launch_bounds__(128, 2) void attn_h(uint32_t* __restrict__ outh) {
    extern __shared__ uint32_t smu[];
    const uint32_t sbase = smem_u32(smu);
    const uint32_t kvbase = sbase + (uint32_t)(64 * QS2) * 4u;
    uint32_t* Ps = smu + PS_OFF;

    const int q0  = blockIdx.x * 64;
    const int h   = blockIdx.y;
    const int kvh = h >> 2;
    const int tid = threadIdx.x;
    const int lane = tid & 31;
    const int wq  = tid >> 5;           // 0..3
    const int g   = lane >> 2;
    const int tig = lane & 3;
    const int rb  = wq * 16;

    const int arow  = (lane & 7) + ((lane & 8) ? 8 : 0);
    const int acsel = (lane & 16) ? 4 : 0;
    const int krow  = (lane & 7) + ((lane & 16) ? 8 : 0);
    const int kcsel = (lane & 8) ? 4 : 0;
    const int vcsel = (lane & 16) ? 1 : 0;

    const float NEG = -1e30f, GUARD = -1e29f;
    // scale * log2(e)
    const __half2 qscale = __float2half2_rn(0.08838834764831845f * 1.4426950408889634f);

    // Q tile: load + pre-scale (fp16)
#pragma unroll
    for (int i = 0; i < 8; ++i) {
        int idx = i * 128 + tid;
        int r = idx >> 4, j4 = (idx & 15) * 4;
        uint4 v = *reinterpret_cast<const uint4*>(&g_qh[(size_t)(q0 + r) * (NHQ * HD / 2) + h * (HD / 2) + j4]);
        __half2* hv = reinterpret_cast<__half2*>(&v);
        hv[0] = __hmul2(hv[0], qscale);
        hv[1] = __hmul2(hv[1], qscale);
        hv[2] = __hmul2(hv[2], qscale);
        hv[3] = __hmul2(hv[3], qscale);
        *reinterpret_cast<uint4*>(&smu[r * QS2 + j4]) = v;
    }

    float m0 = NEG, m1 = NEG, l0 = 0.f, l1 = 0.f;
    float o[16][4];
#pragma unroll
    for (int nf = 0; nf < 16; ++nf)
#pragma unroll
        for (int f = 0; f < 4; ++f) o[nf][f] = 0.f;

    int lo = q0 - (WIN - 1); if (lo < 0) lo = 0;
    const int kb_lo = lo >> 6;
    const int kb_hi = q0 >> 6;

    const uint32_t qfrag = sbase + (uint32_t)((rb + arow) * QS2 + acsel) * 4u;
    const uint32_t pfrag = sbase + (uint32_t)(PS_OFF + (rb + arow) * PS2 + acsel) * 4u;

#define AISSUE(t0_, buf_)                                                             \
    do {                                                                              \
        uint32_t kb_ = kvbase + (uint32_t)((buf_) * KV_TILE) * 4u;                    \
        uint32_t vb_ = kvbase + (uint32_t)((2 + (buf_)) * KV_TILE) * 4u;              \
        _Pragma("unroll")                                                             \
        for (int i = 0; i < 8; ++i) {                                                 \
            int idx = tid + i * 128;                                                  \
            int r = idx >> 4, c = (idx & 15) * 4;                                     \
            cp16(kb_ + (uint32_t)(r * KVS + c) * 4u,                                  \
                 &g_kh[(size_t)((t0_) + r) * (NKV * HD / 2) + kvh * (HD / 2) + c]);   \
        }                                                                             \
        _Pragma("unroll")                                                             \
        for (int i = 0; i < 8; ++i) {                                                 \
            int idx = tid + i * 128;                                                  \
            int r = idx >> 4, c = (idx & 15) * 4;                                     \
            cp16(vb_ + (uint32_t)(r * KVS + c) * 4u,                                  \
                 &g_vh[(size_t)((t0_) + r) * (NKV * HD / 2) + kvh * (HD / 2) + c]);   \
        }                                                                             \
        CP_COMMIT();                                                                  \
    } while (0)

    AISSUE(kb_lo * 64, 0);

    for (int kb = kb_lo; kb <= kb_hi; ++kb) {
        const int t0 = kb * 64;
        const int buf = (kb - kb_lo) & 1;
        if (kb < kb_hi) AISSUE((kb + 1) * 64, buf ^ 1);
        else            CP_COMMIT();
        CP_WAIT1();
        __syncthreads();

        const uint32_t kbuf = kvbase + (uint32_t)(buf * KV_TILE) * 4u;
        const uint32_t vbuf = kvbase + (uint32_t)((2 + buf) * KV_TILE) * 4u;

        // ---- S = Q @ K^T (log2-scaled) ----
        float s[8][4];
#pragma unroll
        for (int nf = 0; nf < 8; ++nf)
#pragma unroll
            for (int f = 0; f < 4; ++f) s[nf][f] = 0.f;

#pragma unroll
        for (int ks = 0; ks < 8; ++ks) {
            uint32_t a[4];
            ldsm_x4(a, qfrag + (uint32_t)(ks * 8) * 4u);
#pragma unroll
            for (int nf = 0; nf < 8; nf += 2) {
                uint32_t b[4];
                ldsm_x4(b, kbuf + (uint32_t)((nf * 8 + krow) * KVS + ks * 8 + kcsel) * 4u);
                mma_h16(s[nf],     a, b);
                mma_h16(s[nf + 1], a, b + 2);
            }
        }

        // ---- mask ----
        const int r0g = q0 + rb + g, r1g = r0g + 8;
#pragma unroll
        for (int nf = 0; nf < 8; ++nf) {
            int c0 = t0 + nf * 8 + 2 * tig;
            int c1 = c0 + 1;
            bool ok00 = (c0 <= r0g) && (r0g - c0 < WIN);
            bool ok01 = (c1 <= r0g) && (r0g - c1 < WIN);
            bool ok10 = (c0 <= r1g) && (r1g - c0 < WIN);
            bool ok11 = (c1 <= r1g) && (r1g - c1 < WIN);
            s[nf][0] = ok00 ? s[nf][0] : NEG;
            s[nf][1] = ok01 ? s[nf][1] : NEG;
            s[nf][2] = ok10 ? s[nf][2] : NEG;
            s[nf][3] = ok11 ? s[nf][3] : NEG;
        }

        // ---- online softmax (exp2 domain) ----
        float mt0 = NEG, mt1 = NEG;
#pragma unroll
        for (int nf = 0; nf < 8; ++nf) {
            mt0 = fmaxf(mt0, fmaxf(s[nf][0], s[nf][1]));
            mt1 = fmaxf(mt1, fmaxf(s[nf][2], s[nf][3]));
        }
        mt0 = fmaxf(mt0, __shfl_xor_sync(0xffffffffu, mt0, 1));
        mt0 = fmaxf(mt0, __shfl_xor_sync(0xffffffffu, mt0, 2));
        mt1 = fmaxf(mt1, __shfl_xor_sync(0xffffffffu, mt1, 1));
        mt1 = fmaxf(mt1, __shfl_xor_sync(0xffffffffu, mt1, 2));

        float mn0 = fmaxf(m0, mt0), mn1 = fmaxf(m1, mt1);
        float esc0 = (m0 > GUARD) ? exp2f(m0 - mn0) : 0.f;
        float esc1 = (m1 > GUARD) ? exp2f(m1 - mn1) : 0.f;

        float rs0 = 0.f, rs1 = 0.f;
#pragma unroll
        for (int nf = 0; nf < 8; ++nf) {
            float p00 = (s[nf][0] > GUARD) ? exp2f(s[nf][0] - mn0) : 0.f;
            float p01 = (s[nf][1] > GUARD) ? exp2f(s[nf][1] - mn0) : 0.f;
            float p10 = (s[nf][2] > GUARD) ? exp2f(s[nf][2] - mn1) : 0.f;
            float p11 = (s[nf][3] > GUARD) ? exp2f(s[nf][3] - mn1) : 0.f;
            rs0 += p00 + p01;
            rs1 += p10 + p11;
            Ps[(rb + g) * PS2 + nf * 4 + tig]     = pack2(p00, p01);
            Ps[(rb + g + 8) * PS2 + nf * 4 + tig] = pack2(p10, p11);
        }
        rs0 += __shfl_xor_sync(0xffffffffu, rs0, 1);
        rs0 += __shfl_xor_sync(0xffffffffu, rs0, 2);
        rs1 += __shfl_xor_sync(0xffffffffu, rs1, 1);
        rs1 += __shfl_xor_sync(0xffffffffu, rs1, 2);

        l0 = l0 * esc0 + rs0; m0 = mn0;
        l1 = l1 * esc1 + rs1; m1 = mn1;

#pragma unroll
        for (int nf = 0; nf < 16; ++nf) {
            o[nf][0] *= esc0; o[nf][1] *= esc0;
            o[nf][2] *= esc1; o[nf][3] *= esc1;
        }
        __syncwarp(0xffffffffu);

        // ---- O += P @ V ----
#pragma unroll
        for (int ks = 0; ks < 4; ++ks) {
            uint32_t a[4];
            ldsm_x4(a, pfrag + (uint32_t)(ks * 8) * 4u);
#pragma unroll
            for (int nf = 0; nf < 16; nf += 2) {
                uint32_t b[4];
                ldsm_x4_t(b, vbuf + (uint32_t)((ks * 16 + arow) * KVS + (nf + vcsel) * 4) * 4u);
                mma_h16(o[nf],     a, b);
                mma_h16(o[nf + 1], a, b + 2);
            }
        }
        __syncthreads();
    }
#undef AISSUE

    // ---- epilogue ----
    const float inv0 = 1.f / l0, inv1 = 1.f / l1;
    const int qr0 = q0 + rb + g, qr1 = qr0 + 8;
#pragma unroll
    for (int nf = 0; nf < 16; ++nf) {
        int c2 = h * (HD / 2) + nf * 4 + tig;
        outh[(size_t)qr0 * (NHQ * HD / 2) + c2] = pack2(o[nf][0] * inv0, o[nf][1] * inv0);
        outh[(size_t)qr1 * (NHQ * HD / 2) + c2] = pack2(o[nf][2] * inv1, o[nf][3] * inv1);
    }
}

// ---------------------------------------------------------------------------
extern "C" void kernel_launch(void* const* d_in, const int* in_sizes, int n_in,
                              void* d_out, int out_size) {
    const float* hs  = (const float*)d_in[0];
    const float* fc  = (const float*)d_in[1];
    const int*   pos = (const int*)d_in[4];
    const float* Wq  = (const float*)d_in[5];
    const float* Wk  = (const float*)d_in[6];
    const float* Wv  = (const float*)d_in[7];
    const float* Wo  = (const float*)d_in[8];
    float* out = (float*)d_out;

    __half *hsh;
    uint32_t *attnh, *wqp, *wkp, *wvp, *wop;
    cudaGetSymbolAddress((void**)&hsh,   g_hsh);
    cudaGetSymbolAddress((void**)&attnh, g_attnh);
    cudaGetSymbolAddress((void**)&wqp,   g_wqp);
    cudaGetSymbolAddress((void**)&wkp,   g_wkp);
    cudaGetSymbolAddress((void**)&wvp,   g_wvp);
    cudaGetSymbolAddress((void**)&wop,   g_wop);

    conv_half<<<(S_LEN * HID) / (256 * 8), 256>>>(hs, hsh);
    pack_all<<<(SEG_Q + 2 * SEG_K + SEG_O) / 256, 256>>>(Wq, Wk, Wv, Wo);

    constexpr int SMEM_QKV = 3 * (A_U32 + 16 * (128 + 8)) * 4;
    constexpr int SMEM_O   = 3 * (A_U32 + 16 * (256 + 8)) * 4;
    cudaFuncSetAttribute((const void*)gemm_h<4, 1>, cudaFuncAttributeMaxDynamicSharedMemorySize, SMEM_QKV);
    cudaFuncSetAttribute((const void*)gemm_h<8, 0>, cudaFuncAttributeMaxDynamicSharedMemorySize, SMEM_O);
    cudaFuncSetAttribute((const void*)attn_h, cudaFuncAttributeMaxDynamicSharedMemorySize, ATT_SMEM);

    // fused QKV + RoPE
    gemm_h<4, 1><<<dim3(24, 16), 256, SMEM_QKV>>>(hsh, HID, wqp, 16, wkp, 4, wvp,
                                                  nullptr, fc, pos);

    // attention: 64 q-rows per CTA, 4 warps, 2 CTAs/SM
    attn_h<<<dim3(S_LEN / 64, NHQ), 128, ATT_SMEM>>>(attnh);

    // O projection
    gemm_h<8, 0><<<dim3(8, 16), 256, SMEM_O>>>((const __half*)attnh, NHQ * HD, wop, 8,
                                               nullptr, 0, nullptr, out, nullptr, nullptr);
}

// round 12
// speedup vs baseline: 1.1934x; 1.1702x over previous
#include <cuda_runtime.h>
#include <cuda_fp16.h>
#include <cstdint>
#include <math.h>

#define S_LEN 2048
#define HID   2048
#define NHQ   16
#define NKV   4
#define HD    128
#define WIN   1024

// ---------------- scratch (no cudaMalloc allowed) ----------------
__device__ __half   g_hsh[S_LEN * HID];
__device__ uint32_t g_qh[S_LEN * (NHQ * HD) / 2];
__device__ uint32_t g_kh[S_LEN * (NKV * HD) / 2];
__device__ uint32_t g_vh[S_LEN * (NKV * HD) / 2];
__device__ uint32_t g_attnh[S_LEN * (NHQ * HD) / 2];
__device__ uint32_t g_wqp[(HID / 2) * (NHQ * HD)];
__device__ uint32_t g_wkp[(HID / 2) * (NKV * HD)];
__device__ uint32_t g_wvp[(HID / 2) * (NKV * HD)];
__device__ uint32_t g_wop[((NHQ * HD) / 2) * HID];

__device__ __forceinline__ uint32_t pack2(float a, float b) {
    __half2 h = __floats2half2_rn(a, b);
    return *reinterpret_cast<uint32_t*>(&h);
}
__device__ __forceinline__ void mma_h16(float c[4], const uint32_t a[4], const uint32_t b[2]) {
    asm volatile("mma.sync.aligned.m16n8k16.row.col.f32.f16.f16.f32 "
        "{%0,%1,%2,%3}, {%4,%5,%6,%7}, {%8,%9}, {%0,%1,%2,%3};"
        : "+f"(c[0]), "+f"(c[1]), "+f"(c[2]), "+f"(c[3])
        : "r"(a[0]), "r"(a[1]), "r"(a[2]), "r"(a[3]), "r"(b[0]), "r"(b[1]));
}
__device__ __forceinline__ void ldsm_x4(uint32_t r[4], uint32_t addr) {
    asm volatile("ldmatrix.sync.aligned.m8n8.x4.shared.b16 {%0,%1,%2,%3}, [%4];"
        : "=r"(r[0]), "=r"(r[1]), "=r"(r[2]), "=r"(r[3]) : "r"(addr));
}
__device__ __forceinline__ void ldsm_x4_t(uint32_t r[4], uint32_t addr) {
    asm volatile("ldmatrix.sync.aligned.m8n8.x4.trans.shared.b16 {%0,%1,%2,%3}, [%4];"
        : "=r"(r[0]), "=r"(r[1]), "=r"(r[2]), "=r"(r[3]) : "r"(addr));
}
__device__ __forceinline__ uint32_t smem_u32(const void* p) {
    uint32_t a;
    asm("{ .reg .u64 t; cvta.to.shared.u64 t, %1; cvt.u32.u64 %0, t; }" : "=r"(a) : "l"(p));
    return a;
}
__device__ __forceinline__ void cp16(uint32_t s, const void* g) {
    asm volatile("cp.async.ca.shared.global [%0], [%1], 16;" :: "r"(s), "l"(g));
}
#define CP_COMMIT() asm volatile("cp.async.commit_group;" ::: "memory")
#define CP_WAIT1()  asm volatile("cp.async.wait_group 1;" ::: "memory")

// ---------------------------------------------------------------------------
__global__ void conv_half(const float* __restrict__ src, __half* __restrict__ dst) {
    int i = (blockIdx.x * blockDim.x + threadIdx.x) * 8;
    float4 v0 = *reinterpret_cast<const float4*>(src + i);
    float4 v1 = *reinterpret_cast<const float4*>(src + i + 4);
    uint4 o = { pack2(v0.x, v0.y), pack2(v0.z, v0.w), pack2(v1.x, v1.y), pack2(v1.z, v1.w) };
    *reinterpret_cast<uint4*>(dst + i) = o;
}

#define SEG_Q ((HID / 2) * (NHQ * HD) / 4)
#define SEG_K ((HID / 2) * (NKV * HD) / 4)
#define SEG_O (((NHQ * HD) / 2) * HID / 4)

__global__ void pack_all(const float* __restrict__ Wq, const float* __restrict__ Wk,
                         const float* __restrict__ Wv, const float* __restrict__ Wo) {
    int u = blockIdx.x * blockDim.x + threadIdx.x;
    const float* W; uint32_t* Wp; int N;
    if (u < SEG_Q)                     { W = Wq; Wp = g_wqp; N = NHQ * HD; }
    else if (u < SEG_Q + SEG_K)        { W = Wk; Wp = g_wkp; N = NKV * HD; u -= SEG_Q; }
    else if (u < SEG_Q + 2 * SEG_K)    { W = Wv; Wp = g_wvp; N = NKV * HD; u -= SEG_Q + SEG_K; }
    else                               { W = Wo; Wp = g_wop; N = HID;      u -= SEG_Q + 2 * SEG_K; }
    int nc4 = N >> 2;
    int r2 = u / nc4, c = (u % nc4) * 4;
    float4 a = *reinterpret_cast<const float4*>(&W[(size_t)(2 * r2) * N + c]);
    float4 b = *reinterpret_cast<const float4*>(&W[(size_t)(2 * r2 + 1) * N + c]);
    uint4 o = { pack2(a.x, b.x), pack2(a.y, b.y), pack2(a.z, b.z), pack2(a.w, b.w) };
    *reinterpret_cast<uint4*>(&Wp[(size_t)r2 * N + c]) = o;
}

// ---------------------------------------------------------------------------
// fp16 cp.async GEMM, CTA 128x128 (NI=4), 8 warps, K-tile 32, 3 stages,
// __launch_bounds__(256, 2): 2 CTAs/SM (16 warps) for latency hiding.
// EPI==0: fp32 out. EPI==1: fused QKV + RoPE, fp16 out.
// ---------------------------------------------------------------------------
#define AS2 20
#define A_U32 (128 * AS2)

template<int NI, int EPI>
__global__ __launch_bounds__(256, 2) void gemm_h(const __half* __restrict__ Ah, int K,
                                                 const uint32_t* __restrict__ Wp0, int nb0,
                                                 const uint32_t* __restrict__ Wp1, int nb1,
                                                 const uint32_t* __restrict__ Wp2,
                                                 float* __restrict__ Cout, int NOUT,
                                                 const float* __restrict__ fc,
                                                 const int* __restrict__ pos) {
    constexpr int TN  = NI * 32;
    constexpr int BS2 = TN + 8;
    constexpr int B_U32 = 16 * BS2;
    constexpr int STG = A_U32 + B_U32;
    constexpr int BCP = TN / 64;

    extern __shared__ uint32_t smg[];
    const uint32_t sbase = smem_u32(smg);

    const int tid  = threadIdx.x;
    const int lane = tid & 31;
    const int wid  = tid >> 5;
    const int wm   = wid & 1;
    const int wn   = wid >> 1;
    const int g    = lane >> 2;
    const int tig  = lane & 3;
    const int brow = blockIdx.y * 128;

    const int arow = (lane & 7) + ((lane & 8) ? 8 : 0);
    const int acsel = (lane & 16) ? 4 : 0;

    const uint32_t* Wp; int N, cloc, dest = 0;
    {
        int bx = blockIdx.x;
        if (bx < nb0)            { Wp = Wp0; N = (EPI ? NHQ * HD : NOUT); cloc = bx * TN; dest = 0; }
        else if (bx < nb0 + nb1) { Wp = Wp1; N = NKV * HD; cloc = (bx - nb0) * TN; dest = 1; }
        else                     { Wp = Wp2; N = NKV * HD; cloc = (bx - nb0 - nb1) * TN; dest = 2; }
    }

    float acc[4][NI][4];
#pragma unroll
    for (int mi = 0; mi < 4; ++mi)
#pragma unroll
        for (int ni = 0; ni < NI; ++ni)
#pragma unroll
            for (int f = 0; f < 4; ++f) acc[mi][ni][f] = 0.f;

    const int iters = K / 32;

#define ISSUE_STAGE(st, k0)                                                          \
    do {                                                                             \
        uint32_t soff = sbase + (uint32_t)((st) * STG) * 4u;                         \
        _Pragma("unroll")                                                            \
        for (int i = 0; i < 2; ++i) {                                                \
            int idx = tid + i * 256;                                                 \
            int r = idx >> 2, ch = idx & 3;                                          \
            cp16(soff + (uint32_t)(r * AS2 * 4 + ch * 16),                           \
                 &Ah[(size_t)(brow + r) * K + (k0) + ch * 8]);                       \
        }                                                                            \
        _Pragma("unroll")                                                            \
        for (int i = 0; i < BCP; ++i) {                                              \
            int idx = tid + i * 256;                                                 \
            int r = idx / (TN / 4), ch = idx % (TN / 4);                             \
            cp16(soff + (uint32_t)(A_U32 * 4 + r * BS2 * 4 + ch * 16),               \
                 &Wp[(size_t)((k0) / 2 + r) * N + cloc + ch * 4]);                   \
        }                                                                            \
        CP_COMMIT();                                                                 \
    } while (0)

    ISSUE_STAGE(0, 0);
    ISSUE_STAGE(1, 32);

    for (int kt = 0; kt < iters; ++kt) {
        CP_WAIT1();
        __syncthreads();

        if (kt + 2 < iters) {
            ISSUE_STAGE((kt + 2) % 3, (kt + 2) * 32);
        } else {
            CP_COMMIT();
        }

        const uint32_t stg_base = sbase + (uint32_t)((kt % 3) * STG) * 4u;
        const uint32_t* Bs = smg + (kt % 3) * STG + A_U32;

#pragma unroll
        for (int kk = 0; kk < 2; ++kk) {
            const int kb2 = kk * 8;
            uint32_t af[4][4], bf[NI][2];
#pragma unroll
            for (int mi = 0; mi < 4; ++mi) {
                int r0 = wm * 64 + mi * 16 + arow;
                ldsm_x4(af[mi], stg_base + (uint32_t)(r0 * AS2 + kb2 + acsel) * 4u);
            }
#pragma unroll
            for (int ni = 0; ni < NI; ++ni) {
                int c0 = wn * (NI * 8) + ni * 8 + g;
                bf[ni][0] = Bs[(kb2 + tig) * BS2 + c0];
                bf[ni][1] = Bs[(kb2 + tig + 4) * BS2 + c0];
            }
#pragma unroll
            for (int mi = 0; mi < 4; ++mi)
#pragma unroll
                for (int ni = 0; ni < NI; ++ni)
                    mma_h16(acc[mi][ni], af[mi], bf[ni]);
        }
        __syncthreads();
    }
#undef ISSUE_STAGE

    if (EPI == 0) {
#pragma unroll
        for (int mi = 0; mi < 4; ++mi) {
            int r0 = brow + wm * 64 + mi * 16 + g;
#pragma unroll
            for (int ni = 0; ni < NI; ++ni) {
                int c0 = cloc + wn * (NI * 8) + ni * 8 + 2 * tig;
                float2 v0 = make_float2(acc[mi][ni][0], acc[mi][ni][1]);
                float2 v1 = make_float2(acc[mi][ni][2], acc[mi][ni][3]);
                *reinterpret_cast<float2*>(&Cout[(size_t)r0 * N + c0])       = v0;
                *reinterpret_cast<float2*>(&Cout[(size_t)(r0 + 8) * N + c0]) = v1;
            }
        }
    } else {
        uint32_t* dst = (dest == 0) ? g_qh : (dest == 1) ? g_kh : g_vh;
        const int rstr = (dest == 0) ? (NHQ * HD / 2) : (NKV * HD / 2);
#pragma unroll
        for (int mi = 0; mi < 4; ++mi) {
            int r0 = brow + wm * 64 + mi * 16 + g;
            int r1 = r0 + 8;
            int p0 = pos[r0], p1 = pos[r1];
#pragma unroll
            for (int ni = 0; ni < NI; ++ni) {
                int c0 = cloc + wn * (NI * 8) + ni * 8 + 2 * tig;
                float a0 = acc[mi][ni][0], b0 = acc[mi][ni][1];
                float a1 = acc[mi][ni][2], b1 = acc[mi][ni][3];
                if (dest < 2) {
                    int dcol = c0 & (HD - 1);
                    float2 cs0 = *reinterpret_cast<const float2*>(&fc[(size_t)p0 * HD + dcol]);
                    float2 cs1 = *reinterpret_cast<const float2*>(&fc[(size_t)p1 * HD + dcol]);
                    float na0 = a0 * cs0.x - b0 * cs0.y;
                    float nb0 = a0 * cs0.y + b0 * cs0.x;
                    float na1 = a1 * cs1.x - b1 * cs1.y;
                    float nb1 = a1 * cs1.y + b1 * cs1.x;
                    a0 = na0; b0 = nb0; a1 = na1; b1 = nb1;
                }
                dst[(size_t)r0 * rstr + (c0 >> 1)] = pack2(a0, b0);
                dst[(size_t)r1 * rstr + (c0 >> 1)] = pack2(a1, b1);
            }
        }
    }
}

// ---------------------------------------------------------------------------
// Flash attention (unchanged from R11): 64 q-rows/CTA, 4 warps, 2 CTAs/SM,
// exp2-domain softmax with Q pre-scaled by scale*log2e.
// ---------------------------------------------------------------------------
#define QS2 68
#define KVS 68
#define PS2 36
#define KV_TILE (64 * KVS)
#define PS_OFF (64 * QS2 + 4 * KV_TILE)
#define ATT_SMEM ((PS_OFF + 64 * PS2) * 4)

__global__ __launch_bounds__(128, 2) void attn_h(uint32_t* __restrict__ outh) {
    extern __shared__ uint32_t smu[];
    const uint32_t sbase = smem_u32(smu);
    const uint32_t kvbase = sbase + (uint32_t)(64 * QS2) * 4u;
    uint32_t* Ps = smu + PS_OFF;

    const int q0  = blockIdx.x * 64;
    const int h   = blockIdx.y;
    const int kvh = h >> 2;
    const int tid = threadIdx.x;
    const int lane = tid & 31;
    const int wq  = tid >> 5;
    const int g   = lane >> 2;
    const int tig = lane & 3;
    const int rb  = wq * 16;

    const int arow  = (lane & 7) + ((lane & 8) ? 8 : 0);
    const int acsel = (lane & 16) ? 4 : 0;
    const int krow  = (lane & 7) + ((lane & 16) ? 8 : 0);
    const int kcsel = (lane & 8) ? 4 : 0;
    const int vcsel = (lane & 16) ? 1 : 0;

    const float NEG = -1e30f, GUARD = -1e29f;
    const __half2 qscale = __float2half2_rn(0.08838834764831845f * 1.4426950408889634f);

#pragma unroll
    for (int i = 0; i < 8; ++i) {
        int idx = i * 128 + tid;
        int r = idx >> 4, j4 = (idx & 15) * 4;
        uint4 v = *reinterpret_cast<const uint4*>(&g_qh[(size_t)(q0 + r) * (NHQ * HD / 2) + h * (HD / 2) + j4]);
        __half2* hv = reinterpret_cast<__half2*>(&v);
        hv[0] = __hmul2(hv[0], qscale);
        hv[1] = __hmul2(hv[1], qscale);
        hv[2] = __hmul2(hv[2], qscale);
        hv[3] = __hmul2(hv[3], qscale);
        *reinterpret_cast<uint4*>(&smu[r * QS2 + j4]) = v;
    }

    float m0 = NEG, m1 = NEG, l0 = 0.f, l1 = 0.f;
    float o[16][4];
#pragma unroll
    for (int nf = 0; nf < 16; ++nf)
#pragma unroll
        for (int f = 0; f < 4; ++f) o[nf][f] = 0.f;

    int lo = q0 - (WIN - 1); if (lo < 0) lo = 0;
    const int kb_lo = lo >> 6;
    const int kb_hi = q0 >> 6;

    const uint32_t qfrag = sbase + (uint32_t)((rb + arow) * QS2 + acsel) * 4u;
    const uint32_t pfrag = sbase + (uint32_t)(PS_OFF + (rb + arow) * PS2 + acsel) * 4u;

#define AISSUE(t0_, buf_)                                                             \
    do {                                                                              \
        uint32_t kb_ = kvbase + (uint32_t)((buf_) * KV_TILE) * 4u;                    \
        uint32_t vb_ = kvbase + (uint32_t)((2 + (buf_)) * KV_TILE) * 4u;              \
        _Pragma("unroll")                                                             \
        for (int i = 0; i < 8; ++i) {                                                 \
            int idx = tid + i * 128;                                                  \
            int r = idx >> 4, c = (idx & 15) * 4;                                     \
            cp16(kb_ + (uint32_t)(r * KVS + c) * 4u,                                  \
                 &g_kh[(size_t)((t0_) + r) * (NKV * HD / 2) + kvh * (HD / 2) + c]);   \
        }                                                                             \
        _Pragma("unroll")                                                             \
        for (int i = 0; i < 8; ++i) {                                                 \
            int idx = tid + i * 128;                                                  \
            int r = idx >> 4, c = (idx & 15) * 4;                                     \
            cp16(vb_ + (uint32_t)(r * KVS + c) * 4u,                                  \
                 &g_vh[(size_t)((t0_) + r) * (NKV * HD / 2) + kvh * (HD / 2) + c]);   \
        }                                                                             \
        CP_COMMIT();                                                                  \
    } while (0)

    AISSUE(kb_lo * 64, 0);

    for (int kb = kb_lo; kb <= kb_hi; ++kb) {
        const int t0 = kb * 64;
        const int buf = (kb - kb_lo) & 1;
        if (kb < kb_hi) AISSUE((kb + 1) * 64, buf ^ 1);
        else            CP_COMMIT();
        CP_WAIT1();
        __syncthreads();

        const uint32_t kbuf = kvbase + (uint32_t)(buf * KV_TILE) * 4u;
        const uint32_t vbuf = kvbase + (uint32_t)((2 + buf) * KV_TILE) * 4u;

        float s[8][4];
#pragma unroll
        for (int nf = 0; nf < 8; ++nf)
#pragma unroll
            for (int f = 0; f < 4; ++f) s[nf][f] = 0.f;

#pragma unroll
        for (int ks = 0; ks < 8; ++ks) {
            uint32_t a[4];
            ldsm_x4(a, qfrag + (uint32_t)(ks * 8) * 4u);
#pragma unroll
            for (int nf = 0; nf < 8; nf += 2) {
                uint32_t b[4];
                ldsm_x4(b, kbuf + (uint32_t)((nf * 8 + krow) * KVS + ks * 8 + kcsel) * 4u);
                mma_h16(s[nf],     a, b);
                mma_h16(s[nf + 1], a, b + 2);
            }
        }

        const int r0g = q0 + rb + g, r1g = r0g + 8;
#pragma unroll
        for (int nf = 0; nf < 8; ++nf) {
            int c0 = t0 + nf * 8 + 2 * tig;
            int c1 = c0 + 1;
            bool ok00 = (c0 <= r0g) && (r0g - c0 < WIN);
            bool ok01 = (c1 <= r0g) && (r0g - c1 < WIN);
            bool ok10 = (c0 <= r1g) && (r1g - c0 < WIN);
            bool ok11 = (c1 <= r1g) && (r1g - c1 < WIN);
            s[nf][0] = ok00 ? s[nf][0] : NEG;
            s[nf][1] = ok01 ? s[nf][1] : NEG;
            s[nf][2] = ok10 ? s[nf][2] : NEG;
            s[nf][3] = ok11 ? s[nf][3] : NEG;
        }

        float mt0 = NEG, mt1 = NEG;
#pragma unroll
        for (int nf = 0; nf < 8; ++nf) {
            mt0 = fmaxf(mt0, fmaxf(s[nf][0], s[nf][1]));
            mt1 = fmaxf(mt1, fmaxf(s[nf][2], s[nf][3]));
        }
        mt0 = fmaxf(mt0, __shfl_xor_sync(0xffffffffu, mt0, 1));
        mt0 = fmaxf(mt0, __shfl_xor_sync(0xffffffffu, mt0, 2));
        mt1 = fmaxf(mt1, __shfl_xor_sync(0xffffffffu, mt1, 1));
        mt1 = fmaxf(mt1, __shfl_xor_sync(0xffffffffu, mt1, 2));

        float mn0 = fmaxf(m0, mt0), mn1 = fmaxf(m1, mt1);
        float esc0 = (m0 > GUARD) ? exp2f(m0 - mn0) : 0.f;
        float esc1 = (m1 > GUARD) ? exp2f(m1 - mn1) : 0.f;

        float rs0 = 0.f, rs1 = 0.f;
#pragma unroll
        for (int nf = 0; nf < 8; ++nf) {
            float p00 = (s[nf][0] > GUARD) ? exp2f(s[nf][0] - mn0) : 0.f;
            float p01 = (s[nf][1] > GUARD) ? exp2f(s[nf][1] - mn0) : 0.f;
            float p10 = (s[nf][2] > GUARD) ? exp2f(s[nf][2] - mn1) : 0.f;
            float p11 = (s[nf][3] > GUARD) ? exp2f(s[nf][3] - mn1) : 0.f;
            rs0 += p00 + p01;
            rs1 += p10 + p11;
            Ps[(rb + g) * PS2 + nf * 4 + tig]     = pack2(p00, p01);
            Ps[(rb + g + 8) * PS2 + nf * 4 + tig] = pack2(p10, p11);
        }
        rs0 += __shfl_xor_sync(0xffffffffu, rs0, 1);
        rs0 += __shfl_xor_sync(0xffffffffu, rs0, 2);
        rs1 += __shfl_xor_sync(0xffffffffu, rs1, 1);
        rs1 += __shfl_xor_sync(0xffffffffu, rs1, 2);

        l0 = l0 * esc0 + rs0; m0 = mn0;
        l1 = l1 * esc1 + rs1; m1 = mn1;

#pragma unroll
        for (int nf = 0; nf < 16; ++nf) {
            o[nf][0] *= esc0; o[nf][1] *= esc0;
            o[nf][2] *= esc1; o[nf][3] *= esc1;
        }
        __syncwarp(0xffffffffu);

#pragma unroll
        for (int ks = 0; ks < 4; ++ks) {
            uint32_t a[4];
            ldsm_x4(a, pfrag + (uint32_t)(ks * 8) * 4u);
#pragma unroll
            for (int nf = 0; nf < 16; nf += 2) {
                uint32_t b[4];
                ldsm_x4_t(b, vbuf + (uint32_t)((ks * 16 + arow) * KVS + (nf + vcsel) * 4) * 4u);
                mma_h16(o[nf],     a, b);
                mma_h16(o[nf + 1], a, b + 2);
            }
        }
        __syncthreads();
    }
#undef AISSUE

    const float inv0 = 1.f / l0, inv1 = 1.f / l1;
    const int qr0 = q0 + rb + g, qr1 = qr0 + 8;
#pragma unroll
    for (int nf = 0; nf < 16; ++nf) {
        int c2 = h * (HD / 2) + nf * 4 + tig;
        outh[(size_t)qr0 * (NHQ * HD / 2) + c2] = pack2(o[nf][0] * inv0, o[nf][1] * inv0);
        outh[(size_t)qr1 * (NHQ * HD / 2) + c2] = pack2(o[nf][2] * inv1, o[nf][3] * inv1);
    }
}

// ---------------------------------------------------------------------------
extern "C" void kernel_launch(void* const* d_in, const int* in_sizes, int n_in,
                              void* d_out, int out_size) {
    const float* hs  = (const float*)d_in[0];
    const float* fc  = (const float*)d_in[1];
    const int*   pos = (const int*)d_in[4];
    const float* Wq  = (const float*)d_in[5];
    const float* Wk  = (const float*)d_in[6];
    const float* Wv  = (const float*)d_in[7];
    const float* Wo  = (const float*)d_in[8];
    float* out = (float*)d_out;

    __half *hsh;
    uint32_t *attnh, *wqp, *wkp, *wvp, *wop;
    cudaGetSymbolAddress((void**)&hsh,   g_hsh);
    cudaGetSymbolAddress((void**)&attnh, g_attnh);
    cudaGetSymbolAddress((void**)&wqp,   g_wqp);
    cudaGetSymbolAddress((void**)&wkp,   g_wkp);
    cudaGetSymbolAddress((void**)&wvp,   g_wvp);
    cudaGetSymbolAddress((void**)&wop,   g_wop);

    conv_half<<<(S_LEN * HID) / (256 * 8), 256>>>(hs, hsh);
    pack_all<<<(SEG_Q + 2 * SEG_K + SEG_O) / 256, 256>>>(Wq, Wk, Wv, Wo);

    constexpr int SMEM_G = 3 * (A_U32 + 16 * (128 + 8)) * 4;   // NI=4, 56832 B
    cudaFuncSetAttribute((const void*)gemm_h<4, 1>, cudaFuncAttributeMaxDynamicSharedMemorySize, SMEM_G);
    cudaFuncSetAttribute((const void*)gemm_h<4, 0>, cudaFuncAttributeMaxDynamicSharedMemorySize, SMEM_G);
    cudaFuncSetAttribute((const void*)attn_h,       cudaFuncAttributeMaxDynamicSharedMemorySize, ATT_SMEM);

    // fused QKV + RoPE: 24 col blocks (16 Q + 4 K + 4 V) x 16 rows, 2 CTAs/SM
    gemm_h<4, 1><<<dim3(24, 16), 256, SMEM_G>>>(hsh, HID, wqp, 16, wkp, 4, wvp,
                                                nullptr, 0, fc, pos);

    // attention: 64 q-rows per CTA, 4 warps, 2 CTAs/SM
    attn_h<<<dim3(S_LEN / 64, NHQ), 128, ATT_SMEM>>>(attnh);

    // O projection: NI=4 tiles (16x16 = 256 CTAs), 2 CTAs/SM
    gemm_h<4, 0><<<dim3(16, 16), 256, SMEM_G>>>((const __half*)attnh, NHQ * HD, wop, 16,
                                                nullptr, 0, nullptr, out, HID, nullptr, nullptr);
}

// round 13
// speedup vs baseline: 1.2853x; 1.0770x over previous
#include <cuda_runtime.h>
#include <cuda_fp16.h>
#include <cstdint>
#include <math.h>

#define S_LEN 2048
#define HID   2048
#define NHQ   16
#define NKV   4
#define HD    128
#define WIN   1024

// ---------------- scratch (no cudaMalloc allowed) ----------------
__device__ __half   g_hsh[S_LEN * HID];
__device__ uint32_t g_qh[S_LEN * (NHQ * HD) / 2];
__device__ uint32_t g_kh[S_LEN * (NKV * HD) / 2];
__device__ uint32_t g_vh[S_LEN * (NKV * HD) / 2];
__device__ uint32_t g_attnh[S_LEN * (NHQ * HD) / 2];
__device__ uint32_t g_wqp[(HID / 2) * (NHQ * HD)];
__device__ uint32_t g_wkp[(HID / 2) * (NKV * HD)];
__device__ uint32_t g_wvp[(HID / 2) * (NKV * HD)];
__device__ uint32_t g_wop[((NHQ * HD) / 2) * HID];

__device__ __forceinline__ uint32_t pack2(float a, float b) {
    __half2 h = __floats2half2_rn(a, b);
    return *reinterpret_cast<uint32_t*>(&h);
}
__device__ __forceinline__ void mma_h16(float c[4], const uint32_t a[4], const uint32_t b[2]) {
    asm volatile("mma.sync.aligned.m16n8k16.row.col.f32.f16.f16.f32 "
        "{%0,%1,%2,%3}, {%4,%5,%6,%7}, {%8,%9}, {%0,%1,%2,%3};"
        : "+f"(c[0]), "+f"(c[1]), "+f"(c[2]), "+f"(c[3])
        : "r"(a[0]), "r"(a[1]), "r"(a[2]), "r"(a[3]), "r"(b[0]), "r"(b[1]));
}
__device__ __forceinline__ void ldsm_x4(uint32_t r[4], uint32_t addr) {
    asm volatile("ldmatrix.sync.aligned.m8n8.x4.shared.b16 {%0,%1,%2,%3}, [%4];"
        : "=r"(r[0]), "=r"(r[1]), "=r"(r[2]), "=r"(r[3]) : "r"(addr));
}
__device__ __forceinline__ void ldsm_x4_t(uint32_t r[4], uint32_t addr) {
    asm volatile("ldmatrix.sync.aligned.m8n8.x4.trans.shared.b16 {%0,%1,%2,%3}, [%4];"
        : "=r"(r[0]), "=r"(r[1]), "=r"(r[2]), "=r"(r[3]) : "r"(addr));
}
__device__ __forceinline__ uint32_t smem_u32(const void* p) {
    uint32_t a;
    asm("{ .reg .u64 t; cvta.to.shared.u64 t, %1; cvt.u32.u64 %0, t; }" : "=r"(a) : "l"(p));
    return a;
}
__device__ __forceinline__ void cp16(uint32_t s, const void* g) {
    asm volatile("cp.async.ca.shared.global [%0], [%1], 16;" :: "r"(s), "l"(g));
}
#define CP_COMMIT() asm volatile("cp.async.commit_group;" ::: "memory")
#define CP_WAIT1()  asm volatile("cp.async.wait_group 1;" ::: "memory")

// ---------------------------------------------------------------------------
__global__ void conv_half(const float* __restrict__ src, __half* __restrict__ dst) {
    int i = (blockIdx.x * blockDim.x + threadIdx.x) * 8;
    float4 v0 = *reinterpret_cast<const float4*>(src + i);
    float4 v1 = *reinterpret_cast<const float4*>(src + i + 4);
    uint4 o = { pack2(v0.x, v0.y), pack2(v0.z, v0.w), pack2(v1.x, v1.y), pack2(v1.z, v1.w) };
    *reinterpret_cast<uint4*>(dst + i) = o;
}

#define SEG_Q ((HID / 2) * (NHQ * HD) / 4)
#define SEG_K ((HID / 2) * (NKV * HD) / 4)
#define SEG_O (((NHQ * HD) / 2) * HID / 4)

__global__ void pack_all(const float* __restrict__ Wq, const float* __restrict__ Wk,
                         const float* __restrict__ Wv, const float* __restrict__ Wo) {
    int u = blockIdx.x * blockDim.x + threadIdx.x;
    const float* W; uint32_t* Wp; int N;
    if (u < SEG_Q)                     { W = Wq; Wp = g_wqp; N = NHQ * HD; }
    else if (u < SEG_Q + SEG_K)        { W = Wk; Wp = g_wkp; N = NKV * HD; u -= SEG_Q; }
    else if (u < SEG_Q + 2 * SEG_K)    { W = Wv; Wp = g_wvp; N = NKV * HD; u -= SEG_Q + SEG_K; }
    else                               { W = Wo; Wp = g_wop; N = HID;      u -= SEG_Q + 2 * SEG_K; }
    int nc4 = N >> 2;
    int r2 = u / nc4, c = (u % nc4) * 4;
    float4 a = *reinterpret_cast<const float4*>(&W[(size_t)(2 * r2) * N + c]);
    float4 b = *reinterpret_cast<const float4*>(&W[(size_t)(2 * r2 + 1) * N + c]);
    uint4 o = { pack2(a.x, b.x), pack2(a.y, b.y), pack2(a.z, b.z), pack2(a.w, b.w) };
    *reinterpret_cast<uint4*>(&Wp[(size_t)r2 * N + c]) = o;
}

// ---------------------------------------------------------------------------
// fp16 cp.async GEMM, CTA 128x128, K-tile 64, 3 stages, 2 CTAs/SM.
// EPI==0: fp32 out. EPI==1: fused QKV + RoPE, fp16 out.
// ---------------------------------------------------------------------------
#define AS2 36                   // 32 u32 (64 halves) + 4 pad
#define A_U32 (128 * AS2)        // 4608
#define TNG 128
#define BS2 (TNG + 8)            // 136
#define B_U32 (32 * BS2)         // 4352
#define STG (A_U32 + B_U32)      // 8960 u32 = 35840 B
#define SMEM_G (3 * STG * 4)     // 107520 B

template<int EPI>
__global__ __launch_bounds__(256, 2) void gemm_h(const __half* __restrict__ Ah, int K,
                                                 const uint32_t* __restrict__ Wp0, int nb0,
                                                 const uint32_t* __restrict__ Wp1, int nb1,
                                                 const uint32_t* __restrict__ Wp2,
                                                 float* __restrict__ Cout, int NOUT,
                                                 const float* __restrict__ fc,
                                                 const int* __restrict__ pos) {
    extern __shared__ uint32_t smg[];
    const uint32_t sbase = smem_u32(smg);

    const int tid  = threadIdx.x;
    const int lane = tid & 31;
    const int wid  = tid >> 5;
    const int wm   = wid & 1;
    const int wn   = wid >> 1;
    const int g    = lane >> 2;
    const int tig  = lane & 3;
    const int brow = blockIdx.y * 128;

    const int arow = (lane & 7) + ((lane & 8) ? 8 : 0);
    const int acsel = (lane & 16) ? 4 : 0;

    const uint32_t* Wp; int N, cloc, dest = 0;
    {
        int bx = blockIdx.x;
        if (bx < nb0)            { Wp = Wp0; N = (EPI ? NHQ * HD : NOUT); cloc = bx * TNG; dest = 0; }
        else if (bx < nb0 + nb1) { Wp = Wp1; N = NKV * HD; cloc = (bx - nb0) * TNG; dest = 1; }
        else                     { Wp = Wp2; N = NKV * HD; cloc = (bx - nb0 - nb1) * TNG; dest = 2; }
    }

    float acc[4][4][4];
#pragma unroll
    for (int mi = 0; mi < 4; ++mi)
#pragma unroll
        for (int ni = 0; ni < 4; ++ni)
#pragma unroll
            for (int f = 0; f < 4; ++f) acc[mi][ni][f] = 0.f;

    const int iters = K / 64;

#define ISSUE_STAGE(st, k0)                                                          \
    do {                                                                             \
        uint32_t soff = sbase + (uint32_t)((st) * STG) * 4u;                         \
        _Pragma("unroll")                                                            \
        for (int i = 0; i < 4; ++i) {                                                \
            int idx = tid + i * 256;                                                 \
            int r = idx >> 3, ch = idx & 7;                                          \
            cp16(soff + (uint32_t)(r * AS2 * 4 + ch * 16),                           \
                 &Ah[(size_t)(brow + r) * K + (k0) + ch * 8]);                       \
        }                                                                            \
        _Pragma("unroll")                                                            \
        for (int i = 0; i < 4; ++i) {                                                \
            int idx = tid + i * 256;                                                 \
            int r = idx >> 5, ch = idx & 31;                                         \
            cp16(soff + (uint32_t)(A_U32 * 4 + r * BS2 * 4 + ch * 16),               \
                 &Wp[(size_t)((k0) / 2 + r) * N + cloc + ch * 4]);                   \
        }                                                                            \
        CP_COMMIT();                                                                 \
    } while (0)

    ISSUE_STAGE(0, 0);
    ISSUE_STAGE(1, 64);

    for (int kt = 0; kt < iters; ++kt) {
        CP_WAIT1();
        __syncthreads();

        if (kt + 2 < iters) {
            ISSUE_STAGE((kt + 2) % 3, (kt + 2) * 64);
        } else {
            CP_COMMIT();
        }

        const uint32_t stg_base = sbase + (uint32_t)((kt % 3) * STG) * 4u;
        const uint32_t* Bs = smg + (kt % 3) * STG + A_U32;

#pragma unroll
        for (int kk = 0; kk < 4; ++kk) {
            const int kb2 = kk * 8;
            uint32_t af[4][4], bf[4][2];
#pragma unroll
            for (int mi = 0; mi < 4; ++mi) {
                int r0 = wm * 64 + mi * 16 + arow;
                ldsm_x4(af[mi], stg_base + (uint32_t)(r0 * AS2 + kb2 + acsel) * 4u);
            }
#pragma unroll
            for (int ni = 0; ni < 4; ++ni) {
                int c0 = wn * 32 + ni * 8 + g;
                bf[ni][0] = Bs[(kb2 + tig) * BS2 + c0];
                bf[ni][1] = Bs[(kb2 + tig + 4) * BS2 + c0];
            }
#pragma unroll
            for (int mi = 0; mi < 4; ++mi)
#pragma unroll
                for (int ni = 0; ni < 4; ++ni)
                    mma_h16(acc[mi][ni], af[mi], bf[ni]);
        }
        __syncthreads();
    }
#undef ISSUE_STAGE

    if (EPI == 0) {
#pragma unroll
        for (int mi = 0; mi < 4; ++mi) {
            int r0 = brow + wm * 64 + mi * 16 + g;
#pragma unroll
            for (int ni = 0; ni < 4; ++ni) {
                int c0 = cloc + wn * 32 + ni * 8 + 2 * tig;
                float2 v0 = make_float2(acc[mi][ni][0], acc[mi][ni][1]);
                float2 v1 = make_float2(acc[mi][ni][2], acc[mi][ni][3]);
                *reinterpret_cast<float2*>(&Cout[(size_t)r0 * N + c0])       = v0;
                *reinterpret_cast<float2*>(&Cout[(size_t)(r0 + 8) * N + c0]) = v1;
            }
        }
    } else {
        uint32_t* dst = (dest == 0) ? g_qh : (dest == 1) ? g_kh : g_vh;
        const int rstr = (dest == 0) ? (NHQ * HD / 2) : (NKV * HD / 2);
#pragma unroll
        for (int mi = 0; mi < 4; ++mi) {
            int r0 = brow + wm * 64 + mi * 16 + g;
            int r1 = r0 + 8;
            int p0 = pos[r0], p1 = pos[r1];
#pragma unroll
            for (int ni = 0; ni < 4; ++ni) {
                int c0 = cloc + wn * 32 + ni * 8 + 2 * tig;
                float a0 = acc[mi][ni][0], b0 = acc[mi][ni][1];
                float a1 = acc[mi][ni][2], b1 = acc[mi][ni][3];
                if (dest < 2) {
                    int dcol = c0 & (HD - 1);
                    float2 cs0 = *reinterpret_cast<const float2*>(&fc[(size_t)p0 * HD + dcol]);
                    float2 cs1 = *reinterpret_cast<const float2*>(&fc[(size_t)p1 * HD + dcol]);
                    float na0 = a0 * cs0.x - b0 * cs0.y;
                    float nb0 = a0 * cs0.y + b0 * cs0.x;
                    float na1 = a1 * cs1.x - b1 * cs1.y;
                    float nb1 = a1 * cs1.y + b1 * cs1.x;
                    a0 = na0; b0 = nb0; a1 = na1; b1 = nb1;
                }
                dst[(size_t)r0 * rstr + (c0 >> 1)] = pack2(a0, b0);
                dst[(size_t)r1 * rstr + (c0 >> 1)] = pack2(a1, b1);
            }
        }
    }
}

// ---------------------------------------------------------------------------
// Flash attention: 64 q-rows/CTA, 4 warps, 2 CTAs/SM, exp2 softmax,
// masking applied ONLY on boundary tiles (diag / window edge); no guards
// (every row has >=1 valid key per in-range tile, so row max is finite and
// exp2f(NEG - mn) underflows to exactly 0).
// ---------------------------------------------------------------------------
#define QS2 68
#define KVS 68
#define PS2 36
#define KV_TILE (64 * KVS)
#define PS_OFF (64 * QS2 + 4 * KV_TILE)
#define ATT_SMEM ((PS_OFF + 64 * PS2) * 4)

__global__ __launch_bounds__(128, 2) void attn_h(uint32_t* __restrict__ outh) {
    extern __shared__ uint32_t smu[];
    const uint32_t sbase = smem_u32(smu);
    const uint32_t kvbase = sbase + (uint32_t)(64 * QS2) * 4u;
    uint32_t* Ps = smu + PS_OFF;

    const int q0  = blockIdx.x * 64;
    const int h   = blockIdx.y;
    const int kvh = h >> 2;
    const int tid = threadIdx.x;
    const int lane = tid & 31;
    const int wq  = tid >> 5;
    const int g   = lane >> 2;
    const int tig = lane & 3;
    const int rb  = wq * 16;

    const int arow  = (lane & 7) + ((lane & 8) ? 8 : 0);
    const int acsel = (lane & 16) ? 4 : 0;
    const int krow  = (lane & 7) + ((lane & 16) ? 8 : 0);
    const int kcsel = (lane & 8) ? 4 : 0;
    const int vcsel = (lane & 16) ? 1 : 0;

    const float NEG = -1e30f;
    const __half2 qscale = __float2half2_rn(0.08838834764831845f * 1.4426950408889634f);

#pragma unroll
    for (int i = 0; i < 8; ++i) {
        int idx = i * 128 + tid;
        int r = idx >> 4, j4 = (idx & 15) * 4;
        uint4 v = *reinterpret_cast<const uint4*>(&g_qh[(size_t)(q0 + r) * (NHQ * HD / 2) + h * (HD / 2) + j4]);
        __half2* hv = reinterpret_cast<__half2*>(&v);
        hv[0] = __hmul2(hv[0], qscale);
        hv[1] = __hmul2(hv[1], qscale);
        hv[2] = __hmul2(hv[2], qscale);
        hv[3] = __hmul2(hv[3], qscale);
        *reinterpret_cast<uint4*>(&smu[r * QS2 + j4]) = v;
    }

    float m0 = NEG, m1 = NEG, l0 = 0.f, l1 = 0.f;
    float o[16][4];
#pragma unroll
    for (int nf = 0; nf < 16; ++nf)
#pragma unroll
        for (int f = 0; f < 4; ++f) o[nf][f] = 0.f;

    int lo = q0 - (WIN - 1); if (lo < 0) lo = 0;
    const int kb_lo = lo >> 6;
    const int kb_hi = q0 >> 6;

    const uint32_t qfrag = sbase + (uint32_t)((rb + arow) * QS2 + acsel) * 4u;
    const uint32_t pfrag = sbase + (uint32_t)(PS_OFF + (rb + arow) * PS2 + acsel) * 4u;

#define AISSUE(t0_, buf_)                                                             \
    do {                                                                              \
        uint32_t kb_ = kvbase + (uint32_t)((buf_) * KV_TILE) * 4u;                    \
        uint32_t vb_ = kvbase + (uint32_t)((2 + (buf_)) * KV_TILE) * 4u;              \
        _Pragma("unroll")                                                             \
        for (int i = 0; i < 8; ++i) {                                                 \
            int idx = tid + i * 128;                                                  \
            int r = idx >> 4, c = (idx & 15) * 4;                                     \
            cp16(kb_ + (uint32_t)(r * KVS + c) * 4u,                                  \
                 &g_kh[(size_t)((t0_) + r) * (NKV * HD / 2) + kvh * (HD / 2) + c]);   \
        }                                                                             \
        _Pragma("unroll")                                                             \
        for (int i = 0; i < 8; ++i) {                                                 \
            int idx = tid + i * 128;                                                  \
            int r = idx >> 4, c = (idx & 15) * 4;                                     \
            cp16(vb_ + (uint32_t)(r * KVS + c) * 4u,                                  \
                 &g_vh[(size_t)((t0_) + r) * (NKV * HD / 2) + kvh * (HD / 2) + c]);   \
        }                                                                             \
        CP_COMMIT();                                                                  \
    } while (0)

    AISSUE(kb_lo * 64, 0);

    for (int kb = kb_lo; kb <= kb_hi; ++kb) {
        const int t0 = kb * 64;
        const int buf = (kb - kb_lo) & 1;
        if (kb < kb_hi) AISSUE((kb + 1) * 64, buf ^ 1);
        else            CP_COMMIT();
        CP_WAIT1();
        __syncthreads();

        const uint32_t kbuf = kvbase + (uint32_t)(buf * KV_TILE) * 4u;
        const uint32_t vbuf = kvbase + (uint32_t)((2 + buf) * KV_TILE) * 4u;

        float s[8][4];
#pragma unroll
        for (int nf = 0; nf < 8; ++nf)
#pragma unroll
            for (int f = 0; f < 4; ++f) s[nf][f] = 0.f;

#pragma unroll
        for (int ks = 0; ks < 8; ++ks) {
            uint32_t a[4];
            ldsm_x4(a, qfrag + (uint32_t)(ks * 8) * 4u);
#pragma unroll
            for (int nf = 0; nf < 8; nf += 2) {
                uint32_t b[4];
                ldsm_x4(b, kbuf + (uint32_t)((nf * 8 + krow) * KVS + ks * 8 + kcsel) * 4u);
                mma_h16(s[nf],     a, b);
                mma_h16(s[nf + 1], a, b + 2);
            }
        }

        // ---- mask only on boundary tiles ----
        if (kb == kb_hi || t0 < lo) {
            const int r0g = q0 + rb + g, r1g = r0g + 8;
#pragma unroll
            for (int nf = 0; nf < 8; ++nf) {
                int c0 = t0 + nf * 8 + 2 * tig;
                int c1 = c0 + 1;
                bool ok00 = (c0 <= r0g) && (r0g - c0 < WIN);
                bool ok01 = (c1 <= r0g) && (r0g - c1 < WIN);
                bool ok10 = (c0 <= r1g) && (r1g - c0 < WIN);
                bool ok11 = (c1 <= r1g) && (r1g - c1 < WIN);
                s[nf][0] = ok00 ? s[nf][0] : NEG;
                s[nf][1] = ok01 ? s[nf][1] : NEG;
                s[nf][2] = ok10 ? s[nf][2] : NEG;
                s[nf][3] = ok11 ? s[nf][3] : NEG;
            }
        }

        float mt0 = NEG, mt1 = NEG;
#pragma unroll
        for (int nf = 0; nf < 8; ++nf) {
            mt0 = fmaxf(mt0, fmaxf(s[nf][0], s[nf][1]));
            mt1 = fmaxf(mt1, fmaxf(s[nf][2], s[nf][3]));
        }
        mt0 = fmaxf(mt0, __shfl_xor_sync(0xffffffffu, mt0, 1));
        mt0 = fmaxf(mt0, __shfl_xor_sync(0xffffffffu, mt0, 2));
        mt1 = fmaxf(mt1, __shfl_xor_sync(0xffffffffu, mt1, 1));
        mt1 = fmaxf(mt1, __shfl_xor_sync(0xffffffffu, mt1, 2));

        float mn0 = fmaxf(m0, mt0), mn1 = fmaxf(m1, mt1);
        float esc0 = exp2f(m0 - mn0);   // m0=NEG on first tile -> underflow to 0
        float esc1 = exp2f(m1 - mn1);

        float rs0 = 0.f, rs1 = 0.f;
#pragma unroll
        for (int nf = 0; nf < 8; ++nf) {
            float p00 = exp2f(s[nf][0] - mn0);   // masked s=NEG -> 0
            float p01 = exp2f(s[nf][1] - mn0);
            float p10 = exp2f(s[nf][2] - mn1);
            float p11 = exp2f(s[nf][3] - mn1);
            rs0 += p00 + p01;
            rs1 += p10 + p11;
            Ps[(rb + g) * PS2 + nf * 4 + tig]     = pack2(p00, p01);
            Ps[(rb + g + 8) * PS2 + nf * 4 + tig] = pack2(p10, p11);
        }
        rs0 += __shfl_xor_sync(0xffffffffu, rs0, 1);
        rs0 += __shfl_xor_sync(0xffffffffu, rs0, 2);
        rs1 += __shfl_xor_sync(0xffffffffu, rs1, 1);
        rs1 += __shfl_xor_sync(0xffffffffu, rs1, 2);

        l0 = l0 * esc0 + rs0; m0 = mn0;
        l1 = l1 * esc1 + rs1; m1 = mn1;

#pragma unroll
        for (int nf = 0; nf < 16; ++nf) {
            o[nf][0] *= esc0; o[nf][1] *= esc0;
            o[nf][2] *= esc1; o[nf][3] *= esc1;
        }
        __syncwarp(0xffffffffu);

#pragma unroll
        for (int ks = 0; ks < 4; ++ks) {
            uint32_t a[4];
            ldsm_x4(a, pfrag + (uint32_t)(ks * 8) * 4u);
#pragma unroll
            for (int nf = 0; nf < 16; nf += 2) {
                uint32_t b[4];
                ldsm_x4_t(b, vbuf + (uint32_t)((ks * 16 + arow) * KVS + (nf + vcsel) * 4) * 4u);
                mma_h16(o[nf],     a, b);
                mma_h16(o[nf + 1], a, b + 2);
            }
        }
        __syncthreads();
    }
#undef AISSUE

    const float inv0 = 1.f / l0, inv1 = 1.f / l1;
    const int qr0 = q0 + rb + g, qr1 = qr0 + 8;
#pragma unroll
    for (int nf = 0; nf < 16; ++nf) {
        int c2 = h * (HD / 2) + nf * 4 + tig;
        outh[(size_t)qr0 * (NHQ * HD / 2) + c2] = pack2(o[nf][0] * inv0, o[nf][1] * inv0);
        outh[(size_t)qr1 * (NHQ * HD / 2) + c2] = pack2(o[nf][2] * inv1, o[nf][3] * inv1);
    }
}

// ---------------------------------------------------------------------------
extern "C" void kernel_launch(void* const* d_in, const int* in_sizes, int n_in,
                              void* d_out, int out_size) {
    const float* hs  = (const float*)d_in[0];
    const float* fc  = (const float*)d_in[1];
    const int*   pos = (const int*)d_in[4];
    const float* Wq  = (const float*)d_in[5];
    const float* Wk  = (const float*)d_in[6];
    const float* Wv  = (const float*)d_in[7];
    const float* Wo  = (const float*)d_in[8];
    float* out = (float*)d_out;

    __half *hsh;
    uint32_t *attnh, *wqp, *wkp, *wvp, *wop;
    cudaGetSymbolAddress((void**)&hsh,   g_hsh);
    cudaGetSymbolAddress((void**)&attnh, g_attnh);
    cudaGetSymbolAddress((void**)&wqp,   g_wqp);
    cudaGetSymbolAddress((void**)&wkp,   g_wkp);
    cudaGetSymbolAddress((void**)&wvp,   g_wvp);
    cudaGetSymbolAddress((void**)&wop,   g_wop);

    conv_half<<<(S_LEN * HID) / (256 * 8), 256>>>(hs, hsh);
    pack_all<<<(SEG_Q + 2 * SEG_K + SEG_O) / 256, 256>>>(Wq, Wk, Wv, Wo);

    cudaFuncSetAttribute((const void*)gemm_h<1>, cudaFuncAttributeMaxDynamicSharedMemorySize, SMEM_G);
    cudaFuncSetAttribute((const void*)gemm_h<0>, cudaFuncAttributeMaxDynamicSharedMemorySize, SMEM_G);
    cudaFuncSetAttribute((const void*)attn_h,    cudaFuncAttributeMaxDynamicSharedMemorySize, ATT_SMEM);

    // fused QKV + RoPE: 24 col blocks (16 Q + 4 K + 4 V) x 16 rows, 2 CTAs/SM
    gemm_h<1><<<dim3(24, 16), 256, SMEM_G>>>(hsh, HID, wqp, 16, wkp, 4, wvp,
                                             nullptr, 0, fc, pos);

    // attention: 64 q-rows per CTA, 4 warps, 2 CTAs/SM
    attn_h<<<dim3(S_LEN / 64, NHQ), 128, ATT_SMEM>>>(attnh);

    // O projection: 16x16 = 256 CTAs, 2 CTAs/SM
    gemm_h<0><<<dim3(16, 16), 256, SMEM_G>>>((const __half*)attnh, NHQ * HD, wop, 16,
                                             nullptr, 0, nullptr, out, HID, nullptr, nullptr);
}

// round 14
// speedup vs baseline: 1.4460x; 1.1250x over previous
#include <cuda_runtime.h>
#include <cuda_fp16.h>
#include <cstdint>
#include <math.h>

#define S_LEN 2048
#define HID   2048
#define NHQ   16
#define NKV   4
#define HD    128
#define WIN   1024

// ---------------- scratch (no cudaMalloc allowed) ----------------
__device__ __half   g_hsh[S_LEN * HID];
__device__ uint32_t g_qh[S_LEN * (NHQ * HD) / 2];
__device__ uint32_t g_kh[S_LEN * (NKV * HD) / 2];
__device__ uint32_t g_vh[S_LEN * (NKV * HD) / 2];
__device__ uint32_t g_attnh[S_LEN * (NHQ * HD) / 2];
__device__ uint32_t g_wqp[(HID / 2) * (NHQ * HD)];
__device__ uint32_t g_wkp[(HID / 2) * (NKV * HD)];
__device__ uint32_t g_wvp[(HID / 2) * (NKV * HD)];
__device__ uint32_t g_wop[((NHQ * HD) / 2) * HID];

__device__ __forceinline__ uint32_t pack2(float a, float b) {
    __half2 h = __floats2half2_rn(a, b);
    return *reinterpret_cast<uint32_t*>(&h);
}
__device__ __forceinline__ void mma_h16(float c[4], const uint32_t a[4], const uint32_t b[2]) {
    asm volatile("mma.sync.aligned.m16n8k16.row.col.f32.f16.f16.f32 "
        "{%0,%1,%2,%3}, {%4,%5,%6,%7}, {%8,%9}, {%0,%1,%2,%3};"
        : "+f"(c[0]), "+f"(c[1]), "+f"(c[2]), "+f"(c[3])
        : "r"(a[0]), "r"(a[1]), "r"(a[2]), "r"(a[3]), "r"(b[0]), "r"(b[1]));
}
__device__ __forceinline__ void ldsm_x4(uint32_t r[4], uint32_t addr) {
    asm volatile("ldmatrix.sync.aligned.m8n8.x4.shared.b16 {%0,%1,%2,%3}, [%4];"
        : "=r"(r[0]), "=r"(r[1]), "=r"(r[2]), "=r"(r[3]) : "r"(addr));
}
__device__ __forceinline__ void ldsm_x4_t(uint32_t r[4], uint32_t addr) {
    asm volatile("ldmatrix.sync.aligned.m8n8.x4.trans.shared.b16 {%0,%1,%2,%3}, [%4];"
        : "=r"(r[0]), "=r"(r[1]), "=r"(r[2]), "=r"(r[3]) : "r"(addr));
}
__device__ __forceinline__ uint32_t smem_u32(const void* p) {
    uint32_t a;
    asm("{ .reg .u64 t; cvta.to.shared.u64 t, %1; cvt.u32.u64 %0, t; }" : "=r"(a) : "l"(p));
    return a;
}
__device__ __forceinline__ void cp16(uint32_t s, const void* g) {
    asm volatile("cp.async.ca.shared.global [%0], [%1], 16;" :: "r"(s), "l"(g));
}
#define CP_COMMIT() asm volatile("cp.async.commit_group;" ::: "memory")
#define CP_WAIT1()  asm volatile("cp.async.wait_group 1;" ::: "memory")
#define CP_WAIT0()  asm volatile("cp.async.wait_group 0;" ::: "memory")

// ---------------------------------------------------------------------------
// one-launch prep: hidden-state fp32->fp16 + all 4 weight packs.
// ---------------------------------------------------------------------------
#define CONV_U (S_LEN * HID / 8)
#define SEG_Q ((HID / 2) * (NHQ * HD) / 4)
#define SEG_K ((HID / 2) * (NKV * HD) / 4)
#define SEG_O (((NHQ * HD) / 2) * HID / 4)
#define PREP_U (CONV_U + SEG_Q + 2 * SEG_K + SEG_O)

__global__ void prep_all(const float* __restrict__ hs,
                         const float* __restrict__ Wq, const float* __restrict__ Wk,
                         const float* __restrict__ Wv, const float* __restrict__ Wo) {
    int u = blockIdx.x * blockDim.x + threadIdx.x;
    if (u < CONV_U) {
        int i = u * 8;
        float4 v0 = *reinterpret_cast<const float4*>(hs + i);
        float4 v1 = *reinterpret_cast<const float4*>(hs + i + 4);
        uint4 o = { pack2(v0.x, v0.y), pack2(v0.z, v0.w), pack2(v1.x, v1.y), pack2(v1.z, v1.w) };
        *reinterpret_cast<uint4*>(g_hsh + i) = o;
        return;
    }
    u -= CONV_U;
    const float* W; uint32_t* Wp; int N;
    if (u < SEG_Q)                  { W = Wq; Wp = g_wqp; N = NHQ * HD; }
    else if (u < SEG_Q + SEG_K)     { W = Wk; Wp = g_wkp; N = NKV * HD; u -= SEG_Q; }
    else if (u < SEG_Q + 2 * SEG_K) { W = Wv; Wp = g_wvp; N = NKV * HD; u -= SEG_Q + SEG_K; }
    else                            { W = Wo; Wp = g_wop; N = HID;      u -= SEG_Q + 2 * SEG_K; }
    int nc4 = N >> 2;
    int r2 = u / nc4, c = (u % nc4) * 4;
    float4 a = *reinterpret_cast<const float4*>(&W[(size_t)(2 * r2) * N + c]);
    float4 b = *reinterpret_cast<const float4*>(&W[(size_t)(2 * r2 + 1) * N + c]);
    uint4 o = { pack2(a.x, b.x), pack2(a.y, b.y), pack2(a.z, b.z), pack2(a.w, b.w) };
    *reinterpret_cast<uint4*>(&Wp[(size_t)r2 * N + c]) = o;
}

// ---------------------------------------------------------------------------
// fp16 cp.async GEMM, CTA 128x128, K-tile 64, 3 stages, 2 CTAs/SM.
// ONE barrier per K-tile (stage issue moved after the MMA phase; write
// target (kt+2)%3 == (kt-1)%3 whose readers all passed this iter's barrier).
// ---------------------------------------------------------------------------
#define AS2 36
#define A_U32 (128 * AS2)
#define TNG 128
#define BS2 (TNG + 8)
#define B_U32 (32 * BS2)
#define STG (A_U32 + B_U32)
#define SMEM_G (3 * STG * 4)

template<int EPI>
__global__ __launch_bounds__(256, 2) void gemm_h(const __half* __restrict__ Ah, int K,
                                                 const uint32_t* __restrict__ Wp0, int nb0,
                                                 const uint32_t* __restrict__ Wp1, int nb1,
                                                 const uint32_t* __restrict__ Wp2,
                                                 float* __restrict__ Cout, int NOUT,
                                                 const float* __restrict__ fc,
                                                 const int* __restrict__ pos) {
    extern __shared__ uint32_t smg[];
    const uint32_t sbase = smem_u32(smg);

    const int tid  = threadIdx.x;
    const int lane = tid & 31;
    const int wid  = tid >> 5;
    const int wm   = wid & 1;
    const int wn   = wid >> 1;
    const int g    = lane >> 2;
    const int tig  = lane & 3;
    const int brow = blockIdx.y * 128;

    const int arow = (lane & 7) + ((lane & 8) ? 8 : 0);
    const int acsel = (lane & 16) ? 4 : 0;

    const uint32_t* Wp; int N, cloc, dest = 0;
    {
        int bx = blockIdx.x;
        if (bx < nb0)            { Wp = Wp0; N = (EPI ? NHQ * HD : NOUT); cloc = bx * TNG; dest = 0; }
        else if (bx < nb0 + nb1) { Wp = Wp1; N = NKV * HD; cloc = (bx - nb0) * TNG; dest = 1; }
        else                     { Wp = Wp2; N = NKV * HD; cloc = (bx - nb0 - nb1) * TNG; dest = 2; }
    }

    float acc[4][4][4];
#pragma unroll
    for (int mi = 0; mi < 4; ++mi)
#pragma unroll
        for (int ni = 0; ni < 4; ++ni)
#pragma unroll
            for (int f = 0; f < 4; ++f) acc[mi][ni][f] = 0.f;

    const int iters = K / 64;

#define ISSUE_STAGE(st, k0)                                                          \
    do {                                                                             \
        uint32_t soff = sbase + (uint32_t)((st) * STG) * 4u;                         \
        _Pragma("unroll")                                                            \
        for (int i = 0; i < 4; ++i) {                                                \
            int idx = tid + i * 256;                                                 \
            int r = idx >> 3, ch = idx & 7;                                          \
            cp16(soff + (uint32_t)(r * AS2 * 4 + ch * 16),                           \
                 &Ah[(size_t)(brow + r) * K + (k0) + ch * 8]);                       \
        }                                                                            \
        _Pragma("unroll")                                                            \
        for (int i = 0; i < 4; ++i) {                                                \
            int idx = tid + i * 256;                                                 \
            int r = idx >> 5, ch = idx & 31;                                         \
            cp16(soff + (uint32_t)(A_U32 * 4 + r * BS2 * 4 + ch * 16),               \
                 &Wp[(size_t)((k0) / 2 + r) * N + cloc + ch * 4]);                   \
        }                                                                            \
        CP_COMMIT();                                                                 \
    } while (0)

    ISSUE_STAGE(0, 0);
    ISSUE_STAGE(1, 64);

    for (int kt = 0; kt < iters; ++kt) {
        CP_WAIT1();
        __syncthreads();

        const uint32_t stg_base = sbase + (uint32_t)((kt % 3) * STG) * 4u;
        const uint32_t* Bs = smg + (kt % 3) * STG + A_U32;

#pragma unroll
        for (int kk = 0; kk < 4; ++kk) {
            const int kb2 = kk * 8;
            uint32_t af[4][4], bf[4][2];
#pragma unroll
            for (int mi = 0; mi < 4; ++mi) {
                int r0 = wm * 64 + mi * 16 + arow;
                ldsm_x4(af[mi], stg_base + (uint32_t)(r0 * AS2 + kb2 + acsel) * 4u);
            }
#pragma unroll
            for (int ni = 0; ni < 4; ++ni) {
                int c0 = wn * 32 + ni * 8 + g;
                bf[ni][0] = Bs[(kb2 + tig) * BS2 + c0];
                bf[ni][1] = Bs[(kb2 + tig + 4) * BS2 + c0];
            }
#pragma unroll
            for (int mi = 0; mi < 4; ++mi)
#pragma unroll
                for (int ni = 0; ni < 4; ++ni)
                    mma_h16(acc[mi][ni], af[mi], bf[ni]);
        }

        if (kt + 2 < iters) {
            ISSUE_STAGE((kt + 2) % 3, (kt + 2) * 64);
        } else {
            CP_COMMIT();
        }
    }
#undef ISSUE_STAGE

    if (EPI == 0) {
#pragma unroll
        for (int mi = 0; mi < 4; ++mi) {
            int r0 = brow + wm * 64 + mi * 16 + g;
#pragma unroll
            for (int ni = 0; ni < 4; ++ni) {
                int c0 = cloc + wn * 32 + ni * 8 + 2 * tig;
                float2 v0 = make_float2(acc[mi][ni][0], acc[mi][ni][1]);
                float2 v1 = make_float2(acc[mi][ni][2], acc[mi][ni][3]);
                *reinterpret_cast<float2*>(&Cout[(size_t)r0 * N + c0])       = v0;
                *reinterpret_cast<float2*>(&Cout[(size_t)(r0 + 8) * N + c0]) = v1;
            }
        }
    } else {
        uint32_t* dst = (dest == 0) ? g_qh : (dest == 1) ? g_kh : g_vh;
        const int rstr = (dest == 0) ? (NHQ * HD / 2) : (NKV * HD / 2);
#pragma unroll
        for (int mi = 0; mi < 4; ++mi) {
            int r0 = brow + wm * 64 + mi * 16 + g;
            int r1 = r0 + 8;
            int p0 = pos[r0], p1 = pos[r1];
#pragma unroll
            for (int ni = 0; ni < 4; ++ni) {
                int c0 = cloc + wn * 32 + ni * 8 + 2 * tig;
                float a0 = acc[mi][ni][0], b0 = acc[mi][ni][1];
                float a1 = acc[mi][ni][2], b1 = acc[mi][ni][3];
                if (dest < 2) {
                    int dcol = c0 & (HD - 1);
                    float2 cs0 = *reinterpret_cast<const float2*>(&fc[(size_t)p0 * HD + dcol]);
                    float2 cs1 = *reinterpret_cast<const float2*>(&fc[(size_t)p1 * HD + dcol]);
                    float na0 = a0 * cs0.x - b0 * cs0.y;
                    float nb0 = a0 * cs0.y + b0 * cs0.x;
                    float na1 = a1 * cs1.x - b1 * cs1.y;
                    float nb1 = a1 * cs1.y + b1 * cs1.x;
                    a0 = na0; b0 = nb0; a1 = na1; b1 = nb1;
                }
                dst[(size_t)r0 * rstr + (c0 >> 1)] = pack2(a0, b0);
                dst[(size_t)r1 * rstr + (c0 >> 1)] = pack2(a1, b1);
            }
        }
    }
}

// ---------------------------------------------------------------------------
// Flash attention: 64 q-rows/CTA, 4 warps, SINGLE-buffered 64-row K/V,
// 3 CTAs/SM (smem 60 KB, regs forced to 170). Cross-CTA overlap hides the
// per-tile KV load latency. exp2 softmax, boundary-only masking.
// smem (u32): Q[64*68] | K[64*68] | V[64*68] | P[64*36]
// ---------------------------------------------------------------------------
#define QS2 68
#define KVS 68
#define PS2 36
#define K_OFF (64 * QS2)
#define V_OFF (K_OFF + 64 * KVS)
#define PS_OFF (V_OFF + 64 * KVS)
#define ATT_SMEM ((PS_OFF + 64 * PS2) * 4)

__global__ __launch_bounds__(128, 3) void attn_h(uint32_t* __restrict__ outh) {
    extern __shared__ uint32_t smu[];
    const uint32_t sbase = smem_u32(smu);
    uint32_t* Ps = smu + PS_OFF;

    const int q0  = blockIdx.x * 64;
    const int h   = blockIdx.y;
    const int kvh = h >> 2;
    const int tid = threadIdx.x;
    const int lane = tid & 31;
    const int wq  = tid >> 5;
    const int g   = lane >> 2;
    const int tig = lane & 3;
    const int rb  = wq * 16;

    const int arow  = (lane & 7) + ((lane & 8) ? 8 : 0);
    const int acsel = (lane & 16) ? 4 : 0;
    const int krow  = (lane & 7) + ((lane & 16) ? 8 : 0);
    const int kcsel = (lane & 8) ? 4 : 0;
    const int vcsel = (lane & 16) ? 1 : 0;

    const float NEG = -1e30f;
    const __half2 qscale = __float2half2_rn(0.08838834764831845f * 1.4426950408889634f);

#pragma unroll
    for (int i = 0; i < 8; ++i) {
        int idx = i * 128 + tid;
        int r = idx >> 4, j4 = (idx & 15) * 4;
        uint4 v = *reinterpret_cast<const uint4*>(&g_qh[(size_t)(q0 + r) * (NHQ * HD / 2) + h * (HD / 2) + j4]);
        __half2* hv = reinterpret_cast<__half2*>(&v);
        hv[0] = __hmul2(hv[0], qscale);
        hv[1] = __hmul2(hv[1], qscale);
        hv[2] = __hmul2(hv[2], qscale);
        hv[3] = __hmul2(hv[3], qscale);
        *reinterpret_cast<uint4*>(&smu[r * QS2 + j4]) = v;
    }

    float m0 = NEG, m1 = NEG, l0 = 0.f, l1 = 0.f;
    float o[16][4];
#pragma unroll
    for (int nf = 0; nf < 16; ++nf)
#pragma unroll
        for (int f = 0; f < 4; ++f) o[nf][f] = 0.f;

    int lo = q0 - (WIN - 1); if (lo < 0) lo = 0;
    const int kb_lo = lo >> 6;
    const int kb_hi = q0 >> 6;

    const uint32_t qfrag = sbase + (uint32_t)((rb + arow) * QS2 + acsel) * 4u;
    const uint32_t pfrag = sbase + (uint32_t)(PS_OFF + (rb + arow) * PS2 + acsel) * 4u;
    const uint32_t kbuf = sbase + (uint32_t)K_OFF * 4u;
    const uint32_t vbuf = sbase + (uint32_t)V_OFF * 4u;

    for (int kb = kb_lo; kb <= kb_hi; ++kb) {
        const int t0 = kb * 64;
        // issue K+V tile loads into the single buffer
#pragma unroll
        for (int i = 0; i < 8; ++i) {
            int idx = tid + i * 128;
            int r = idx >> 4, c = (idx & 15) * 4;
            cp16(kbuf + (uint32_t)(r * KVS + c) * 4u,
                 &g_kh[(size_t)(t0 + r) * (NKV * HD / 2) + kvh * (HD / 2) + c]);
        }
#pragma unroll
        for (int i = 0; i < 8; ++i) {
            int idx = tid + i * 128;
            int r = idx >> 4, c = (idx & 15) * 4;
            cp16(vbuf + (uint32_t)(r * KVS + c) * 4u,
                 &g_vh[(size_t)(t0 + r) * (NKV * HD / 2) + kvh * (HD / 2) + c]);
        }
        CP_COMMIT();
        CP_WAIT0();
        __syncthreads();

        // ---- S = Q @ K^T ----
        float s[8][4];
#pragma unroll
        for (int nf = 0; nf < 8; ++nf)
#pragma unroll
            for (int f = 0; f < 4; ++f) s[nf][f] = 0.f;

#pragma unroll
        for (int ks = 0; ks < 8; ++ks) {
            uint32_t a[4];
            ldsm_x4(a, qfrag + (uint32_t)(ks * 8) * 4u);
#pragma unroll
            for (int nf = 0; nf < 8; nf += 2) {
                uint32_t b[4];
                ldsm_x4(b, kbuf + (uint32_t)((nf * 8 + krow) * KVS + ks * 8 + kcsel) * 4u);
                mma_h16(s[nf],     a, b);
                mma_h16(s[nf + 1], a, b + 2);
            }
        }

        // ---- mask only on boundary tiles ----
        if (kb == kb_hi || t0 < lo) {
            const int r0g = q0 + rb + g, r1g = r0g + 8;
#pragma unroll
            for (int nf = 0; nf < 8; ++nf) {
                int c0 = t0 + nf * 8 + 2 * tig;
                int c1 = c0 + 1;
                bool ok00 = (c0 <= r0g) && (r0g - c0 < WIN);
                bool ok01 = (c1 <= r0g) && (r0g - c1 < WIN);
                bool ok10 = (c0 <= r1g) && (r1g - c0 < WIN);
                bool ok11 = (c1 <= r1g) && (r1g - c1 < WIN);
                s[nf][0] = ok00 ? s[nf][0] : NEG;
                s[nf][1] = ok01 ? s[nf][1] : NEG;
                s[nf][2] = ok10 ? s[nf][2] : NEG;
                s[nf][3] = ok11 ? s[nf][3] : NEG;
            }
        }

        // ---- online softmax (exp2 domain) ----
        float mt0 = NEG, mt1 = NEG;
#pragma unroll
        for (int nf = 0; nf < 8; ++nf) {
            mt0 = fmaxf(mt0, fmaxf(s[nf][0], s[nf][1]));
            mt1 = fmaxf(mt1, fmaxf(s[nf][2], s[nf][3]));
        }
        mt0 = fmaxf(mt0, __shfl_xor_sync(0xffffffffu, mt0, 1));
        mt0 = fmaxf(mt0, __shfl_xor_sync(0xffffffffu, mt0, 2));
        mt1 = fmaxf(mt1, __shfl_xor_sync(0xffffffffu, mt1, 1));
        mt1 = fmaxf(mt1, __shfl_xor_sync(0xffffffffu, mt1, 2));

        float mn0 = fmaxf(m0, mt0), mn1 = fmaxf(m1, mt1);
        float esc0 = exp2f(m0 - mn0);
        float esc1 = exp2f(m1 - mn1);

        float rs0 = 0.f, rs1 = 0.f;
#pragma unroll
        for (int nf = 0; nf < 8; ++nf) {
            float p00 = exp2f(s[nf][0] - mn0);
            float p01 = exp2f(s[nf][1] - mn0);
            float p10 = exp2f(s[nf][2] - mn1);
            float p11 = exp2f(s[nf][3] - mn1);
            rs0 += p00 + p01;
            rs1 += p10 + p11;
            Ps[(rb + g) * PS2 + nf * 4 + tig]     = pack2(p00, p01);
            Ps[(rb + g + 8) * PS2 + nf * 4 + tig] = pack2(p10, p11);
        }
        rs0 += __shfl_xor_sync(0xffffffffu, rs0, 1);
        rs0 += __shfl_xor_sync(0xffffffffu, rs0, 2);
        rs1 += __shfl_xor_sync(0xffffffffu, rs1, 1);
        rs1 += __shfl_xor_sync(0xffffffffu, rs1, 2);

        l0 = l0 * esc0 + rs0; m0 = mn0;
        l1 = l1 * esc1 + rs1; m1 = mn1;

#pragma unroll
        for (int nf = 0; nf < 16; ++nf) {
            o[nf][0] *= esc0; o[nf][1] *= esc0;
            o[nf][2] *= esc1; o[nf][3] *= esc1;
        }
        __syncwarp(0xffffffffu);

        // ---- O += P @ V ----
#pragma unroll
        for (int ks = 0; ks < 4; ++ks) {
            uint32_t a[4];
            ldsm_x4(a, pfrag + (uint32_t)(ks * 8) * 4u);
#pragma unroll
            for (int nf = 0; nf < 16; nf += 2) {
                uint32_t b[4];
                ldsm_x4_t(b, vbuf + (uint32_t)((ks * 16 + arow) * KVS + (nf + vcsel) * 4) * 4u);
                mma_h16(o[nf],     a, b);
                mma_h16(o[nf + 1], a, b + 2);
            }
        }
        __syncthreads();   // all warps done with K/V before next tile overwrites
    }

    const float inv0 = 1.f / l0, inv1 = 1.f / l1;
    const int qr0 = q0 + rb + g, qr1 = qr0 + 8;
#pragma unroll
    for (int nf = 0; nf < 16; ++nf) {
        int c2 = h * (HD / 2) + nf * 4 + tig;
        outh[(size_t)qr0 * (NHQ * HD / 2) + c2] = pack2(o[nf][0] * inv0, o[nf][1] * inv0);
        outh[(size_t)qr1 * (NHQ * HD / 2) + c2] = pack2(o[nf][2] * inv1, o[nf][3] * inv1);
    }
}

// ---------------------------------------------------------------------------
extern "C" void kernel_launch(void* const* d_in, const int* in_sizes, int n_in,
                              void* d_out, int out_size) {
    const float* hs  = (const float*)d_in[0];
    const float* fc  = (const float*)d_in[1];
    const int*   pos = (const int*)d_in[4];
    const float* Wq  = (const float*)d_in[5];
    const float* Wk  = (const float*)d_in[6];
    const float* Wv  = (const float*)d_in[7];
    const float* Wo  = (const float*)d_in[8];
    float* out = (float*)d_out;

    __half *hsh;
    uint32_t *attnh, *wqp, *wkp, *wvp, *wop;
    cudaGetSymbolAddress((void**)&hsh,   g_hsh);
    cudaGetSymbolAddress((void**)&attnh, g_attnh);
    cudaGetSymbolAddress((void**)&wqp,   g_wqp);
    cudaGetSymbolAddress((void**)&wkp,   g_wkp);
    cudaGetSymbolAddress((void**)&wvp,   g_wvp);
    cudaGetSymbolAddress((void**)&wop,   g_wop);

    // single prep launch: convert hs + pack all weights
    prep_all<<<PREP_U / 256, 256>>>(hs, Wq, Wk, Wv, Wo);

    cudaFuncSetAttribute((const void*)gemm_h<1>, cudaFuncAttributeMaxDynamicSharedMemorySize, SMEM_G);
    cudaFuncSetAttribute((const void*)gemm_h<0>, cudaFuncAttributeMaxDynamicSharedMemorySize, SMEM_G);
    cudaFuncSetAttribute((const void*)attn_h,    cudaFuncAttributeMaxDynamicSharedMemorySize, ATT_SMEM);

    // fused QKV + RoPE: 24 col blocks (16 Q + 4 K + 4 V) x 16 rows, 2 CTAs/SM
    gemm_h<1><<<dim3(24, 16), 256, SMEM_G>>>(hsh, HID, wqp, 16, wkp, 4, wvp,
                                             nullptr, 0, fc, pos);

    // attention: 64 q-rows per CTA, 4 warps, 3 CTAs/SM
    attn_h<<<dim3(S_LEN / 64, NHQ), 128, ATT_SMEM>>>(attnh);

    // O projection: 16x16 = 256 CTAs, 2 CTAs/SM
    gemm_h<0><<<dim3(16, 16), 256, SMEM_G>>>((const __half*)attnh, NHQ * HD, wop, 16,
                                             nullptr, 0, nullptr, out, HID, nullptr, nullptr);
}

// round 15
// speedup vs baseline: 1.4741x; 1.0194x over previous
#include <cuda_runtime.h>
#include <cuda_fp16.h>
#include <cstdint>
#include <math.h>

#define S_LEN 2048
#define HID   2048
#define NHQ   16
#define NKV   4
#define HD    128
#define WIN   1024

// ---------------- scratch (no cudaMalloc allowed) ----------------
__device__ __half   g_hsh[S_LEN * HID];
__device__ uint32_t g_qh[S_LEN * (NHQ * HD) / 2];
__device__ uint32_t g_kh[S_LEN * (NKV * HD) / 2];
__device__ uint32_t g_vh[S_LEN * (NKV * HD) / 2];
__device__ uint32_t g_attnh[S_LEN * (NHQ * HD) / 2];
// fp16 row-major weights: [K][N/2] u32 (u32 = cols n, n+1)
__device__ uint32_t g_wqp[HID * (NHQ * HD) / 2];
__device__ uint32_t g_wkp[HID * (NKV * HD) / 2];
__device__ uint32_t g_wvp[HID * (NKV * HD) / 2];
__device__ uint32_t g_wop[(NHQ * HD) * HID / 2];

__device__ __forceinline__ uint32_t pack2(float a, float b) {
    __half2 h = __floats2half2_rn(a, b);
    return *reinterpret_cast<uint32_t*>(&h);
}
__device__ __forceinline__ void mma_h16(float c[4], const uint32_t a[4], const uint32_t b[2]) {
    asm volatile("mma.sync.aligned.m16n8k16.row.col.f32.f16.f16.f32 "
        "{%0,%1,%2,%3}, {%4,%5,%6,%7}, {%8,%9}, {%0,%1,%2,%3};"
        : "+f"(c[0]), "+f"(c[1]), "+f"(c[2]), "+f"(c[3])
        : "r"(a[0]), "r"(a[1]), "r"(a[2]), "r"(a[3]), "r"(b[0]), "r"(b[1]));
}
__device__ __forceinline__ void ldsm_x4(uint32_t r[4], uint32_t addr) {
    asm volatile("ldmatrix.sync.aligned.m8n8.x4.shared.b16 {%0,%1,%2,%3}, [%4];"
        : "=r"(r[0]), "=r"(r[1]), "=r"(r[2]), "=r"(r[3]) : "r"(addr));
}
__device__ __forceinline__ void ldsm_x4_t(uint32_t r[4], uint32_t addr) {
    asm volatile("ldmatrix.sync.aligned.m8n8.x4.trans.shared.b16 {%0,%1,%2,%3}, [%4];"
        : "=r"(r[0]), "=r"(r[1]), "=r"(r[2]), "=r"(r[3]) : "r"(addr));
}
__device__ __forceinline__ uint32_t smem_u32(const void* p) {
    uint32_t a;
    asm("{ .reg .u64 t; cvta.to.shared.u64 t, %1; cvt.u32.u64 %0, t; }" : "=r"(a) : "l"(p));
    return a;
}
__device__ __forceinline__ void cp16(uint32_t s, const void* g) {
    asm volatile("cp.async.ca.shared.global [%0], [%1], 16;" :: "r"(s), "l"(g));
}
#define CP_COMMIT() asm volatile("cp.async.commit_group;" ::: "memory")
#define CP_WAIT1()  asm volatile("cp.async.wait_group 1;" ::: "memory")
#define CP_WAIT0()  asm volatile("cp.async.wait_group 0;" ::: "memory")

// ---------------------------------------------------------------------------
// one-launch prep: hs fp32->fp16 + all weights to fp16 row-major [K][N/2] u32.
// Unit = one uint4 (8 cols of one k-row).
// ---------------------------------------------------------------------------
#define CONV_U (S_LEN * HID / 8)
#define SEG_Q (HID * (NHQ * HD) / 8)
#define SEG_K (HID * (NKV * HD) / 8)
#define SEG_O ((NHQ * HD) * HID / 8)
#define PREP_U (CONV_U + SEG_Q + 2 * SEG_K + SEG_O)

__global__ void prep_all(const float* __restrict__ hs,
                         const float* __restrict__ Wq, const float* __restrict__ Wk,
                         const float* __restrict__ Wv, const float* __restrict__ Wo) {
    int u = blockIdx.x * blockDim.x + threadIdx.x;
    if (u < CONV_U) {
        int i = u * 8;
        float4 v0 = *reinterpret_cast<const float4*>(hs + i);
        float4 v1 = *reinterpret_cast<const float4*>(hs + i + 4);
        uint4 o = { pack2(v0.x, v0.y), pack2(v0.z, v0.w), pack2(v1.x, v1.y), pack2(v1.z, v1.w) };
        *reinterpret_cast<uint4*>(g_hsh + i) = o;
        return;
    }
    u -= CONV_U;
    const float* W; uint32_t* Wp;
    if (u < SEG_Q)                  { W = Wq; Wp = g_wqp; }
    else if (u < SEG_Q + SEG_K)     { W = Wk; Wp = g_wkp; u -= SEG_Q; }
    else if (u < SEG_Q + 2 * SEG_K) { W = Wv; Wp = g_wvp; u -= SEG_Q + SEG_K; }
    else                            { W = Wo; Wp = g_wop; u -= SEG_Q + 2 * SEG_K; }
    int i = u * 8;   // linear element index (row-major)
    float4 a = *reinterpret_cast<const float4*>(W + i);
    float4 b = *reinterpret_cast<const float4*>(W + i + 4);
    uint4 o = { pack2(a.x, a.y), pack2(a.z, a.w), pack2(b.x, b.y), pack2(b.z, b.w) };
    *reinterpret_cast<uint4*>(Wp + u * 4) = o;
}

// ---------------------------------------------------------------------------
// fp16 cp.async GEMM, CTA 128x128, K-tile 64, 3 stages, 2 CTAs/SM.
// A frags via ldmatrix.x4, B frags via ldmatrix.x4.trans on [k][n] tile.
// One barrier per K-tile.
// ---------------------------------------------------------------------------
#define AS2 36
#define A_U32 (128 * AS2)          // 4608
#define TNG 128
#define BS2 (TNG / 2 + 4)          // 68 u32 per k-row
#define B_U32 (64 * BS2)           // 4352
#define STG (A_U32 + B_U32)        // 8960 u32
#define SMEM_G (3 * STG * 4)

template<int EPI>
__global__ __launch_bounds__(256, 2) void gemm_h(const __half* __restrict__ Ah, int K,
                                                 const uint32_t* __restrict__ Wp0, int nb0,
                                                 const uint32_t* __restrict__ Wp1, int nb1,
                                                 const uint32_t* __restrict__ Wp2,
                                                 float* __restrict__ Cout, int NOUT,
                                                 const float* __restrict__ fc,
                                                 const int* __restrict__ pos) {
    extern __shared__ uint32_t smg[];
    const uint32_t sbase = smem_u32(smg);

    const int tid  = threadIdx.x;
    const int lane = tid & 31;
    const int wid  = tid >> 5;
    const int wm   = wid & 1;
    const int wn   = wid >> 1;
    const int g    = lane >> 2;
    const int tig  = lane & 3;
    const int brow = blockIdx.y * 128;

    const int arow  = (lane & 7) + ((lane & 8) ? 8 : 0);
    const int acsel = (lane & 16) ? 4 : 0;
    const int vcsel = (lane & 16) ? 1 : 0;

    const uint32_t* Wp; int N, cloc, dest = 0;
    {
        int bx = blockIdx.x;
        if (bx < nb0)            { Wp = Wp0; N = (EPI ? NHQ * HD : NOUT); cloc = bx * TNG; dest = 0; }
        else if (bx < nb0 + nb1) { Wp = Wp1; N = NKV * HD; cloc = (bx - nb0) * TNG; dest = 1; }
        else                     { Wp = Wp2; N = NKV * HD; cloc = (bx - nb0 - nb1) * TNG; dest = 2; }
    }
    const int N2 = N >> 1;        // u32 row width of weight matrix
    const int c2loc = cloc >> 1;  // u32 col offset of this tile

    float acc[4][4][4];
#pragma unroll
    for (int mi = 0; mi < 4; ++mi)
#pragma unroll
        for (int ni = 0; ni < 4; ++ni)
#pragma unroll
            for (int f = 0; f < 4; ++f) acc[mi][ni][f] = 0.f;

    const int iters = K / 64;

#define ISSUE_STAGE(st, k0)                                                          \
    do {                                                                             \
        uint32_t soff = sbase + (uint32_t)((st) * STG) * 4u;                         \
        _Pragma("unroll")                                                            \
        for (int i = 0; i < 4; ++i) {                                                \
            int idx = tid + i * 256;                                                 \
            int r = idx >> 3, ch = idx & 7;                                          \
            cp16(soff + (uint32_t)(r * AS2 * 4 + ch * 16),                           \
                 &Ah[(size_t)(brow + r) * K + (k0) + ch * 8]);                       \
        }                                                                            \
        _Pragma("unroll")                                                            \
        for (int i = 0; i < 4; ++i) {                                                \
            int idx = tid + i * 256;                                                 \
            int r = idx >> 4, ch = idx & 15;                                         \
            cp16(soff + (uint32_t)(A_U32 * 4 + r * BS2 * 4 + ch * 16),               \
                 &Wp[(size_t)((k0) + r) * N2 + c2loc + ch * 4]);                     \
        }                                                                            \
        CP_COMMIT();                                                                 \
    } while (0)

    ISSUE_STAGE(0, 0);
    ISSUE_STAGE(1, 64);

    for (int kt = 0; kt < iters; ++kt) {
        CP_WAIT1();
        __syncthreads();

        const uint32_t stg_base = sbase + (uint32_t)((kt % 3) * STG) * 4u;
        const uint32_t bbase = stg_base + (uint32_t)A_U32 * 4u;

#pragma unroll
        for (int kk = 0; kk < 4; ++kk) {
            const int kb2 = kk * 8;
            uint32_t af[4][4], bf[2][4];
#pragma unroll
            for (int mi = 0; mi < 4; ++mi) {
                int r0 = wm * 64 + mi * 16 + arow;
                ldsm_x4(af[mi], stg_base + (uint32_t)(r0 * AS2 + kb2 + acsel) * 4u);
            }
            // B frags: 2 ldsm.trans per kk, each yields 2 n-frags
#pragma unroll
            for (int p = 0; p < 2; ++p)
                ldsm_x4_t(bf[p], bbase + (uint32_t)((kk * 16 + arow) * BS2
                                        + wn * 16 + (2 * p + vcsel) * 4) * 4u);
#pragma unroll
            for (int mi = 0; mi < 4; ++mi) {
                mma_h16(acc[mi][0], af[mi], bf[0]);
                mma_h16(acc[mi][1], af[mi], bf[0] + 2);
                mma_h16(acc[mi][2], af[mi], bf[1]);
                mma_h16(acc[mi][3], af[mi], bf[1] + 2);
            }
        }

        if (kt + 2 < iters) {
            ISSUE_STAGE((kt + 2) % 3, (kt + 2) * 64);
        } else {
            CP_COMMIT();
        }
    }
#undef ISSUE_STAGE

    if (EPI == 0) {
#pragma unroll
        for (int mi = 0; mi < 4; ++mi) {
            int r0 = brow + wm * 64 + mi * 16 + g;
#pragma unroll
            for (int ni = 0; ni < 4; ++ni) {
                int c0 = cloc + wn * 32 + ni * 8 + 2 * tig;
                float2 v0 = make_float2(acc[mi][ni][0], acc[mi][ni][1]);
                float2 v1 = make_float2(acc[mi][ni][2], acc[mi][ni][3]);
                *reinterpret_cast<float2*>(&Cout[(size_t)r0 * N + c0])       = v0;
                *reinterpret_cast<float2*>(&Cout[(size_t)(r0 + 8) * N + c0]) = v1;
            }
        }
    } else {
        uint32_t* dst = (dest == 0) ? g_qh : (dest == 1) ? g_kh : g_vh;
        const int rstr = (dest == 0) ? (NHQ * HD / 2) : (NKV * HD / 2);
#pragma unroll
        for (int mi = 0; mi < 4; ++mi) {
            int r0 = brow + wm * 64 + mi * 16 + g;
            int r1 = r0 + 8;
            int p0 = pos[r0], p1 = pos[r1];
#pragma unroll
            for (int ni = 0; ni < 4; ++ni) {
                int c0 = cloc + wn * 32 + ni * 8 + 2 * tig;
                float a0 = acc[mi][ni][0], b0 = acc[mi][ni][1];
                float a1 = acc[mi][ni][2], b1 = acc[mi][ni][3];
                if (dest < 2) {
                    int dcol = c0 & (HD - 1);
                    float2 cs0 = *reinterpret_cast<const float2*>(&fc[(size_t)p0 * HD + dcol]);
                    float2 cs1 = *reinterpret_cast<const float2*>(&fc[(size_t)p1 * HD + dcol]);
                    float na0 = a0 * cs0.x - b0 * cs0.y;
                    float nb0 = a0 * cs0.y + b0 * cs0.x;
                    float na1 = a1 * cs1.x - b1 * cs1.y;
                    float nb1 = a1 * cs1.y + b1 * cs1.x;
                    a0 = na0; b0 = nb0; a1 = na1; b1 = nb1;
                }
                dst[(size_t)r0 * rstr + (c0 >> 1)] = pack2(a0, b0);
                dst[(size_t)r1 * rstr + (c0 >> 1)] = pack2(a1, b1);
            }
        }
    }
}

// ---------------------------------------------------------------------------
// Flash attention (unchanged R14 winner): 64 q-rows/CTA, 4 warps, 3 CTAs/SM,
// single-buffered K/V, exp2 softmax, boundary-only masking.
// ---------------------------------------------------------------------------
#define QS2 68
#define KVS 68
#define PS2 36
#define K_OFF (64 * QS2)
#define V_OFF (K_OFF + 64 * KVS)
#define PS_OFF (V_OFF + 64 * KVS)
#define ATT_SMEM ((PS_OFF + 64 * PS2) * 4)

__global__ __launch_bounds__(128, 3) void attn_h(uint32_t* __restrict__ outh) {
    extern __shared__ uint32_t smu[];
    const uint32_t sbase = smem_u32(smu);
    uint32_t* Ps = smu + PS_OFF;

    const int q0  = blockIdx.x * 64;
    const int h   = blockIdx.y;
    const int kvh = h >> 2;
    const int tid = threadIdx.x;
    const int lane = tid & 31;
    const int wq  = tid >> 5;
    const int g   = lane >> 2;
    const int tig = lane & 3;
    const int rb  = wq * 16;

    const int arow  = (lane & 7) + ((lane & 8) ? 8 : 0);
    const int acsel = (lane & 16) ? 4 : 0;
    const int krow  = (lane & 7) + ((lane & 16) ? 8 : 0);
    const int kcsel = (lane & 8) ? 4 : 0;
    const int vcsel = (lane & 16) ? 1 : 0;

    const float NEG = -1e30f;
    const __half2 qscale = __float2half2_rn(0.08838834764831845f * 1.4426950408889634f);

#pragma unroll
    for (int i = 0; i < 8; ++i) {
        int idx = i * 128 + tid;
        int r = idx >> 4, j4 = (idx & 15) * 4;
        uint4 v = *reinterpret_cast<const uint4*>(&g_qh[(size_t)(q0 + r) * (NHQ * HD / 2) + h * (HD / 2) + j4]);
        __half2* hv = reinterpret_cast<__half2*>(&v);
        hv[0] = __hmul2(hv[0], qscale);
        hv[1] = __hmul2(hv[1], qscale);
        hv[2] = __hmul2(hv[2], qscale);
        hv[3] = __hmul2(hv[3], qscale);
        *reinterpret_cast<uint4*>(&smu[r * QS2 + j4]) = v;
    }

    float m0 = NEG, m1 = NEG, l0 = 0.f, l1 = 0.f;
    float o[16][4];
#pragma unroll
    for (int nf = 0; nf < 16; ++nf)
#pragma unroll
        for (int f = 0; f < 4; ++f) o[nf][f] = 0.f;

    int lo = q0 - (WIN - 1); if (lo < 0) lo = 0;
    const int kb_lo = lo >> 6;
    const int kb_hi = q0 >> 6;

    const uint32_t qfrag = sbase + (uint32_t)((rb + arow) * QS2 + acsel) * 4u;
    const uint32_t pfrag = sbase + (uint32_t)(PS_OFF + (rb + arow) * PS2 + acsel) * 4u;
    const uint32_t kbuf = sbase + (uint32_t)K_OFF * 4u;
    const uint32_t vbuf = sbase + (uint32_t)V_OFF * 4u;

    for (int kb = kb_lo; kb <= kb_hi; ++kb) {
        const int t0 = kb * 64;
#pragma unroll
        for (int i = 0; i < 8; ++i) {
            int idx = tid + i * 128;
            int r = idx >> 4, c = (idx & 15) * 4;
            cp16(kbuf + (uint32_t)(r * KVS + c) * 4u,
                 &g_kh[(size_t)(t0 + r) * (NKV * HD / 2) + kvh * (HD / 2) + c]);
        }
#pragma unroll
        for (int i = 0; i < 8; ++i) {
            int idx = tid + i * 128;
            int r = idx >> 4, c = (idx & 15) * 4;
            cp16(vbuf + (uint32_t)(r * KVS + c) * 4u,
                 &g_vh[(size_t)(t0 + r) * (NKV * HD / 2) + kvh * (HD / 2) + c]);
        }
        CP_COMMIT();
        CP_WAIT0();
        __syncthreads();

        float s[8][4];
#pragma unroll
        for (int nf = 0; nf < 8; ++nf)
#pragma unroll
            for (int f = 0; f < 4; ++f) s[nf][f] = 0.f;

#pragma unroll
        for (int ks = 0; ks < 8; ++ks) {
            uint32_t a[4];
            ldsm_x4(a, qfrag + (uint32_t)(ks * 8) * 4u);
#pragma unroll
            for (int nf = 0; nf < 8; nf += 2) {
                uint32_t b[4];
                ldsm_x4(b, kbuf + (uint32_t)((nf * 8 + krow) * KVS + ks * 8 + kcsel) * 4u);
                mma_h16(s[nf],     a, b);
                mma_h16(s[nf + 1], a, b + 2);
            }
        }

        if (kb == kb_hi || t0 < lo) {
            const int r0g = q0 + rb + g, r1g = r0g + 8;
#pragma unroll
            for (int nf = 0; nf < 8; ++nf) {
                int c0 = t0 + nf * 8 + 2 * tig;
                int c1 = c0 + 1;
                bool ok00 = (c0 <= r0g) && (r0g - c0 < WIN);
                bool ok01 = (c1 <= r0g) && (r0g - c1 < WIN);
                bool ok10 = (c0 <= r1g) && (r1g - c0 < WIN);
                bool ok11 = (c1 <= r1g) && (r1g - c1 < WIN);
                s[nf][0] = ok00 ? s[nf][0] : NEG;
                s[nf][1] = ok01 ? s[nf][1] : NEG;
                s[nf][2] = ok10 ? s[nf][2] : NEG;
                s[nf][3] = ok11 ? s[nf][3] : NEG;
            }
        }

        float mt0 = NEG, mt1 = NEG;
#pragma unroll
        for (int nf = 0; nf < 8; ++nf) {
            mt0 = fmaxf(mt0, fmaxf(s[nf][0], s[nf][1]));
            mt1 = fmaxf(mt1, fmaxf(s[nf][2], s[nf][3]));
        }
        mt0 = fmaxf(mt0, __shfl_xor_sync(0xffffffffu, mt0, 1));
        mt0 = fmaxf(mt0, __shfl_xor_sync(0xffffffffu, mt0, 2));
        mt1 = fmaxf(mt1, __shfl_xor_sync(0xffffffffu, mt1, 1));
        mt1 = fmaxf(mt1, __shfl_xor_sync(0xffffffffu, mt1, 2));

        float mn0 = fmaxf(m0, mt0), mn1 = fmaxf(m1, mt1);
        float esc0 = exp2f(m0 - mn0);
        float esc1 = exp2f(m1 - mn1);

        float rs0 = 0.f, rs1 = 0.f;
#pragma unroll
        for (int nf = 0; nf < 8; ++nf) {
            float p00 = exp2f(s[nf][0] - mn0);
            float p01 = exp2f(s[nf][1] - mn0);
            float p10 = exp2f(s[nf][2] - mn1);
            float p11 = exp2f(s[nf][3] - mn1);
            rs0 += p00 + p01;
            rs1 += p10 + p11;
            Ps[(rb + g) * PS2 + nf * 4 + tig]     = pack2(p00, p01);
            Ps[(rb + g + 8) * PS2 + nf * 4 + tig] = pack2(p10, p11);
        }
        rs0 += __shfl_xor_sync(0xffffffffu, rs0, 1);
        rs0 += __shfl_xor_sync(0xffffffffu, rs0, 2);
        rs1 += __shfl_xor_sync(0xffffffffu, rs1, 1);
        rs1 += __shfl_xor_sync(0xffffffffu, rs1, 2);

        l0 = l0 * esc0 + rs0; m0 = mn0;
        l1 = l1 * esc1 + rs1; m1 = mn1;

#pragma unroll
        for (int nf = 0; nf < 16; ++nf) {
            o[nf][0] *= esc0; o[nf][1] *= esc0;
            o[nf][2] *= esc1; o[nf][3] *= esc1;
        }
        __syncwarp(0xffffffffu);

#pragma unroll
        for (int ks = 0; ks < 4; ++ks) {
            uint32_t a[4];
            ldsm_x4(a, pfrag + (uint32_t)(ks * 8) * 4u);
#pragma unroll
            for (int nf = 0; nf < 16; nf += 2) {
                uint32_t b[4];
                ldsm_x4_t(b, vbuf + (uint32_t)((ks * 16 + arow) * KVS + (nf + vcsel) * 4) * 4u);
                mma_h16(o[nf],     a, b);
                mma_h16(o[nf + 1], a, b + 2);
            }
        }
        __syncthreads();
    }

    const float inv0 = 1.f / l0, inv1 = 1.f / l1;
    const int qr0 = q0 + rb + g, qr1 = qr0 + 8;
#pragma unroll
    for (int nf = 0; nf < 16; ++nf) {
        int c2 = h * (HD / 2) + nf * 4 + tig;
        outh[(size_t)qr0 * (NHQ * HD / 2) + c2] = pack2(o[nf][0] * inv0, o[nf][1] * inv0);
        outh[(size_t)qr1 * (NHQ * HD / 2) + c2] = pack2(o[nf][2] * inv1, o[nf][3] * inv1);
    }
}

// ---------------------------------------------------------------------------
extern "C" void kernel_launch(void* const* d_in, const int* in_sizes, int n_in,
                              void* d_out, int out_size) {
    const float* hs  = (const float*)d_in[0];
    const float* fc  = (const float*)d_in[1];
    const int*   pos = (const int*)d_in[4];
    const float* Wq  = (const float*)d_in[5];
    const float* Wk  = (const float*)d_in[6];
    const float* Wv  = (const float*)d_in[7];
    const float* Wo  = (const float*)d_in[8];
    float* out = (float*)d_out;

    __half *hsh;
    uint32_t *attnh, *wqp, *wkp, *wvp, *wop;
    cudaGetSymbolAddress((void**)&hsh,   g_hsh);
    cudaGetSymbolAddress((void**)&attnh, g_attnh);
    cudaGetSymbolAddress((void**)&wqp,   g_wqp);
    cudaGetSymbolAddress((void**)&wkp,   g_wkp);
    cudaGetSymbolAddress((void**)&wvp,   g_wvp);
    cudaGetSymbolAddress((void**)&wop,   g_wop);

    prep_all<<<PREP_U / 256, 256>>>(hs, Wq, Wk, Wv, Wo);

    cudaFuncSetAttribute((const void*)gemm_h<1>, cudaFuncAttributeMaxDynamicSharedMemorySize, SMEM_G);
    cudaFuncSetAttribute((const void*)gemm_h<0>, cudaFuncAttributeMaxDynamicSharedMemorySize, SMEM_G);
    cudaFuncSetAttribute((const void*)attn_h,    cudaFuncAttributeMaxDynamicSharedMemorySize, ATT_SMEM);

    // fused QKV + RoPE: 24 col blocks (16 Q + 4 K + 4 V) x 16 rows, 2 CTAs/SM
    gemm_h<1><<<dim3(24, 16), 256, SMEM_G>>>(hsh, HID, wqp, 16, wkp, 4, wvp,
                                             nullptr, 0, fc, pos);

    // attention: 64 q-rows per CTA, 4 warps, 3 CTAs/SM
    attn_h<<<dim3(S_LEN / 64, NHQ), 128, ATT_SMEM>>>(attnh);

    // O projection: 16x16 = 256 CTAs, 2 CTAs/SM
    gemm_h<0><<<dim3(16, 16), 256, SMEM_G>>>((const __half*)attnh, NHQ * HD, wop, 16,
                                             nullptr, 0, nullptr, out, HID, nullptr, nullptr);
}

// round 16
// speedup vs baseline: 1.4956x; 1.0146x over previous
#include <cuda_runtime.h>
#include <cuda_fp16.h>
#include <cstdint>
#include <math.h>

#define S_LEN 2048
#define HID   2048
#define NHQ   16
#define NKV   4
#define HD    128
#define WIN   1024

// ---------------- scratch (no cudaMalloc allowed) ----------------
__device__ __half   g_hsh[S_LEN * HID];
__device__ uint32_t g_qh[S_LEN * (NHQ * HD) / 2];
__device__ uint32_t g_kh[S_LEN * (NKV * HD) / 2];
__device__ uint32_t g_vh[S_LEN * (NKV * HD) / 2];
__device__ uint32_t g_attnh[S_LEN * (NHQ * HD) / 2];
// fp16 row-major weights: [K][N/2] u32 (u32 = cols n, n+1)
__device__ uint32_t g_wqp[HID * (NHQ * HD) / 2];
__device__ uint32_t g_wkp[HID * (NKV * HD) / 2];
__device__ uint32_t g_wvp[HID * (NKV * HD) / 2];
__device__ uint32_t g_wop[(NHQ * HD) * HID / 2];

__device__ __forceinline__ uint32_t pack2(float a, float b) {
    __half2 h = __floats2half2_rn(a, b);
    return *reinterpret_cast<uint32_t*>(&h);
}
__device__ __forceinline__ void mma_h16(float c[4], const uint32_t a[4], const uint32_t b[2]) {
    asm volatile("mma.sync.aligned.m16n8k16.row.col.f32.f16.f16.f32 "
        "{%0,%1,%2,%3}, {%4,%5,%6,%7}, {%8,%9}, {%0,%1,%2,%3};"
        : "+f"(c[0]), "+f"(c[1]), "+f"(c[2]), "+f"(c[3])
        : "r"(a[0]), "r"(a[1]), "r"(a[2]), "r"(a[3]), "r"(b[0]), "r"(b[1]));
}
__device__ __forceinline__ void ldsm_x4(uint32_t r[4], uint32_t addr) {
    asm volatile("ldmatrix.sync.aligned.m8n8.x4.shared.b16 {%0,%1,%2,%3}, [%4];"
        : "=r"(r[0]), "=r"(r[1]), "=r"(r[2]), "=r"(r[3]) : "r"(addr));
}
__device__ __forceinline__ void ldsm_x4_t(uint32_t r[4], uint32_t addr) {
    asm volatile("ldmatrix.sync.aligned.m8n8.x4.trans.shared.b16 {%0,%1,%2,%3}, [%4];"
        : "=r"(r[0]), "=r"(r[1]), "=r"(r[2]), "=r"(r[3]) : "r"(addr));
}
__device__ __forceinline__ uint32_t smem_u32(const void* p) {
    uint32_t a;
    asm("{ .reg .u64 t; cvta.to.shared.u64 t, %1; cvt.u32.u64 %0, t; }" : "=r"(a) : "l"(p));
    return a;
}
__device__ __forceinline__ void cp16(uint32_t s, const void* g) {
    asm volatile("cp.async.ca.shared.global [%0], [%1], 16;" :: "r"(s), "l"(g));
}
#define CP_COMMIT() asm volatile("cp.async.commit_group;" ::: "memory")
#define CP_WAIT1()  asm volatile("cp.async.wait_group 1;" ::: "memory")
#define CP_WAIT0()  asm volatile("cp.async.wait_group 0;" ::: "memory")

// ---------------------------------------------------------------------------
// one-launch prep: hs fp32->fp16 + all weights to fp16 row-major [K][N/2] u32.
// ---------------------------------------------------------------------------
#define CONV_U (S_LEN * HID / 8)
#define SEG_Q (HID * (NHQ * HD) / 8)
#define SEG_K (HID * (NKV * HD) / 8)
#define SEG_O ((NHQ * HD) * HID / 8)
#define PREP_U (CONV_U + SEG_Q + 2 * SEG_K + SEG_O)

__global__ void prep_all(const float* __restrict__ hs,
                         const float* __restrict__ Wq, const float* __restrict__ Wk,
                         const float* __restrict__ Wv, const float* __restrict__ Wo) {
    int u = blockIdx.x * blockDim.x + threadIdx.x;
    if (u < CONV_U) {
        int i = u * 8;
        float4 v0 = *reinterpret_cast<const float4*>(hs + i);
        float4 v1 = *reinterpret_cast<const float4*>(hs + i + 4);
        uint4 o = { pack2(v0.x, v0.y), pack2(v0.z, v0.w), pack2(v1.x, v1.y), pack2(v1.z, v1.w) };
        *reinterpret_cast<uint4*>(g_hsh + i) = o;
        return;
    }
    u -= CONV_U;
    const float* W; uint32_t* Wp;
    if (u < SEG_Q)                  { W = Wq; Wp = g_wqp; }
    else if (u < SEG_Q + SEG_K)     { W = Wk; Wp = g_wkp; u -= SEG_Q; }
    else if (u < SEG_Q + 2 * SEG_K) { W = Wv; Wp = g_wvp; u -= SEG_Q + SEG_K; }
    else                            { W = Wo; Wp = g_wop; u -= SEG_Q + 2 * SEG_K; }
    int i = u * 8;
    float4 a = *reinterpret_cast<const float4*>(W + i);
    float4 b = *reinterpret_cast<const float4*>(W + i + 4);
    uint4 o = { pack2(a.x, a.y), pack2(a.z, a.w), pack2(b.x, b.y), pack2(b.z, b.w) };
    *reinterpret_cast<uint4*>(Wp + u * 4) = o;
}

// ---------------------------------------------------------------------------
// fp16 cp.async GEMM (unchanged R15): CTA 128x128, K-tile 64, 3 stages,
// 2 CTAs/SM, A frags ldmatrix, B frags ldmatrix.trans, one barrier/K-tile.
// ---------------------------------------------------------------------------
#define AS2 36
#define A_U32 (128 * AS2)
#define TNG 128
#define BS2 (TNG / 2 + 4)
#define B_U32 (64 * BS2)
#define STG (A_U32 + B_U32)
#define SMEM_G (3 * STG * 4)

template<int EPI>
__global__ __launch_bounds__(256, 2) void gemm_h(const __half* __restrict__ Ah, int K,
                                                 const uint32_t* __restrict__ Wp0, int nb0,
                                                 const uint32_t* __restrict__ Wp1, int nb1,
                                                 const uint32_t* __restrict__ Wp2,
                                                 float* __restrict__ Cout, int NOUT,
                                                 const float* __restrict__ fc,
                                                 const int* __restrict__ pos) {
    extern __shared__ uint32_t smg[];
    const uint32_t sbase = smem_u32(smg);

    const int tid  = threadIdx.x;
    const int lane = tid & 31;
    const int wid  = tid >> 5;
    const int wm   = wid & 1;
    const int wn   = wid >> 1;
    const int g    = lane >> 2;
    const int tig  = lane & 3;
    const int brow = blockIdx.y * 128;

    const int arow  = (lane & 7) + ((lane & 8) ? 8 : 0);
    const int acsel = (lane & 16) ? 4 : 0;
    const int vcsel = (lane & 16) ? 1 : 0;

    const uint32_t* Wp; int N, cloc, dest = 0;
    {
        int bx = blockIdx.x;
        if (bx < nb0)            { Wp = Wp0; N = (EPI ? NHQ * HD : NOUT); cloc = bx * TNG; dest = 0; }
        else if (bx < nb0 + nb1) { Wp = Wp1; N = NKV * HD; cloc = (bx - nb0) * TNG; dest = 1; }
        else                     { Wp = Wp2; N = NKV * HD; cloc = (bx - nb0 - nb1) * TNG; dest = 2; }
    }
    const int N2 = N >> 1;
    const int c2loc = cloc >> 1;

    float acc[4][4][4];
#pragma unroll
    for (int mi = 0; mi < 4; ++mi)
#pragma unroll
        for (int ni = 0; ni < 4; ++ni)
#pragma unroll
            for (int f = 0; f < 4; ++f) acc[mi][ni][f] = 0.f;

    const int iters = K / 64;

#define ISSUE_STAGE(st, k0)                                                          \
    do {                                                                             \
        uint32_t soff = sbase + (uint32_t)((st) * STG) * 4u;                         \
        _Pragma("unroll")                                                            \
        for (int i = 0; i < 4; ++i) {                                                \
            int idx = tid + i * 256;                                                 \
            int r = idx >> 3, ch = idx & 7;                                          \
            cp16(soff + (uint32_t)(r * AS2 * 4 + ch * 16),                           \
                 &Ah[(size_t)(brow + r) * K + (k0) + ch * 8]);                       \
        }                                                                            \
        _Pragma("unroll")                                                            \
        for (int i = 0; i < 4; ++i) {                                                \
            int idx = tid + i * 256;                                                 \
            int r = idx >> 4, ch = idx & 15;                                         \
            cp16(soff + (uint32_t)(A_U32 * 4 + r * BS2 * 4 + ch * 16),               \
                 &Wp[(size_t)((k0) + r) * N2 + c2loc + ch * 4]);                     \
        }                                                                            \
        CP_COMMIT();                                                                 \
    } while (0)

    ISSUE_STAGE(0, 0);
    ISSUE_STAGE(1, 64);

    for (int kt = 0; kt < iters; ++kt) {
        CP_WAIT1();
        __syncthreads();

        const uint32_t stg_base = sbase + (uint32_t)((kt % 3) * STG) * 4u;
        const uint32_t bbase = stg_base + (uint32_t)A_U32 * 4u;

#pragma unroll
        for (int kk = 0; kk < 4; ++kk) {
            const int kb2 = kk * 8;
            uint32_t af[4][4], bf[2][4];
#pragma unroll
            for (int mi = 0; mi < 4; ++mi) {
                int r0 = wm * 64 + mi * 16 + arow;
                ldsm_x4(af[mi], stg_base + (uint32_t)(r0 * AS2 + kb2 + acsel) * 4u);
            }
#pragma unroll
            for (int p = 0; p < 2; ++p)
                ldsm_x4_t(bf[p], bbase + (uint32_t)((kk * 16 + arow) * BS2
                                        + wn * 16 + (2 * p + vcsel) * 4) * 4u);
#pragma unroll
            for (int mi = 0; mi < 4; ++mi) {
                mma_h16(acc[mi][0], af[mi], bf[0]);
                mma_h16(acc[mi][1], af[mi], bf[0] + 2);
                mma_h16(acc[mi][2], af[mi], bf[1]);
                mma_h16(acc[mi][3], af[mi], bf[1] + 2);
            }
        }

        if (kt + 2 < iters) {
            ISSUE_STAGE((kt + 2) % 3, (kt + 2) * 64);
        } else {
            CP_COMMIT();
        }
    }
#undef ISSUE_STAGE

    if (EPI == 0) {
#pragma unroll
        for (int mi = 0; mi < 4; ++mi) {
            int r0 = brow + wm * 64 + mi * 16 + g;
#pragma unroll
            for (int ni = 0; ni < 4; ++ni) {
                int c0 = cloc + wn * 32 + ni * 8 + 2 * tig;
                float2 v0 = make_float2(acc[mi][ni][0], acc[mi][ni][1]);
                float2 v1 = make_float2(acc[mi][ni][2], acc[mi][ni][3]);
                *reinterpret_cast<float2*>(&Cout[(size_t)r0 * N + c0])       = v0;
                *reinterpret_cast<float2*>(&Cout[(size_t)(r0 + 8) * N + c0]) = v1;
            }
        }
    } else {
        uint32_t* dst = (dest == 0) ? g_qh : (dest == 1) ? g_kh : g_vh;
        const int rstr = (dest == 0) ? (NHQ * HD / 2) : (NKV * HD / 2);
#pragma unroll
        for (int mi = 0; mi < 4; ++mi) {
            int r0 = brow + wm * 64 + mi * 16 + g;
            int r1 = r0 + 8;
            int p0 = pos[r0], p1 = pos[r1];
#pragma unroll
            for (int ni = 0; ni < 4; ++ni) {
                int c0 = cloc + wn * 32 + ni * 8 + 2 * tig;
                float a0 = acc[mi][ni][0], b0 = acc[mi][ni][1];
                float a1 = acc[mi][ni][2], b1 = acc[mi][ni][3];
                if (dest < 2) {
                    int dcol = c0 & (HD - 1);
                    float2 cs0 = *reinterpret_cast<const float2*>(&fc[(size_t)p0 * HD + dcol]);
                    float2 cs1 = *reinterpret_cast<const float2*>(&fc[(size_t)p1 * HD + dcol]);
                    float na0 = a0 * cs0.x - b0 * cs0.y;
                    float nb0 = a0 * cs0.y + b0 * cs0.x;
                    float na1 = a1 * cs1.x - b1 * cs1.y;
                    float nb1 = a1 * cs1.y + b1 * cs1.x;
                    a0 = na0; b0 = nb0; a1 = na1; b1 = nb1;
                }
                dst[(size_t)r0 * rstr + (c0 >> 1)] = pack2(a0, b0);
                dst[(size_t)r1 * rstr + (c0 >> 1)] = pack2(a1, b1);
            }
        }
    }
}

// ---------------------------------------------------------------------------
// Flash attention: 64 q-rows/CTA, 4 warps, 3 CTAs/SM, single-buffered K/V,
// exp2 softmax, boundary-only masking, P KEPT IN REGISTERS (S-accumulator
// fragment layout == PV A-operand fragment layout; no smem round-trip).
// smem (u32): Q[64*68] | K[64*68] | V[64*68]   = 51 KB
// ---------------------------------------------------------------------------
#define QS2 68
#define KVS 68
#define K_OFF (64 * QS2)
#define V_OFF (K_OFF + 64 * KVS)
#define ATT_SMEM ((V_OFF + 64 * KVS) * 4)

__global__ __launch_bounds__(128, 3) void attn_h(uint32_t* __restrict__ outh) {
    extern __shared__ uint32_t smu[];
    const uint32_t sbase = smem_u32(smu);

    const int q0  = blockIdx.x * 64;
    const int h   = blockIdx.y;
    const int kvh = h >> 2;
    const int tid = threadIdx.x;
    const int lane = tid & 31;
    const int wq  = tid >> 5;
    const int g   = lane >> 2;
    const int tig = lane & 3;
    const int rb  = wq * 16;

    const int arow  = (lane & 7) + ((lane & 8) ? 8 : 0);
    const int acsel = (lane & 16) ? 4 : 0;
    const int krow  = (lane & 7) + ((lane & 16) ? 8 : 0);
    const int kcsel = (lane & 8) ? 4 : 0;
    const int vcsel = (lane & 16) ? 1 : 0;

    const float NEG = -1e30f;
    const __half2 qscale = __float2half2_rn(0.08838834764831845f * 1.4426950408889634f);

#pragma unroll
    for (int i = 0; i < 8; ++i) {
        int idx = i * 128 + tid;
        int r = idx >> 4, j4 = (idx & 15) * 4;
        uint4 v = *reinterpret_cast<const uint4*>(&g_qh[(size_t)(q0 + r) * (NHQ * HD / 2) + h * (HD / 2) + j4]);
        __half2* hv = reinterpret_cast<__half2*>(&v);
        hv[0] = __hmul2(hv[0], qscale);
        hv[1] = __hmul2(hv[1], qscale);
        hv[2] = __hmul2(hv[2], qscale);
        hv[3] = __hmul2(hv[3], qscale);
        *reinterpret_cast<uint4*>(&smu[r * QS2 + j4]) = v;
    }

    float m0 = NEG, m1 = NEG, l0 = 0.f, l1 = 0.f;
    float o[16][4];
#pragma unroll
    for (int nf = 0; nf < 16; ++nf)
#pragma unroll
        for (int f = 0; f < 4; ++f) o[nf][f] = 0.f;

    int lo = q0 - (WIN - 1); if (lo < 0) lo = 0;
    const int kb_lo = lo >> 6;
    const int kb_hi = q0 >> 6;

    const uint32_t qfrag = sbase + (uint32_t)((rb + arow) * QS2 + acsel) * 4u;
    const uint32_t kbuf = sbase + (uint32_t)K_OFF * 4u;
    const uint32_t vbuf = sbase + (uint32_t)V_OFF * 4u;

    for (int kb = kb_lo; kb <= kb_hi; ++kb) {
        const int t0 = kb * 64;
#pragma unroll
        for (int i = 0; i < 8; ++i) {
            int idx = tid + i * 128;
            int r = idx >> 4, c = (idx & 15) * 4;
            cp16(kbuf + (uint32_t)(r * KVS + c) * 4u,
                 &g_kh[(size_t)(t0 + r) * (NKV * HD / 2) + kvh * (HD / 2) + c]);
        }
#pragma unroll
        for (int i = 0; i < 8; ++i) {
            int idx = tid + i * 128;
            int r = idx >> 4, c = (idx & 15) * 4;
            cp16(vbuf + (uint32_t)(r * KVS + c) * 4u,
                 &g_vh[(size_t)(t0 + r) * (NKV * HD / 2) + kvh * (HD / 2) + c]);
        }
        CP_COMMIT();
        CP_WAIT0();
        __syncthreads();

        // ---- S = Q @ K^T ----
        float s[8][4];
#pragma unroll
        for (int nf = 0; nf < 8; ++nf)
#pragma unroll
            for (int f = 0; f < 4; ++f) s[nf][f] = 0.f;

#pragma unroll
        for (int ks = 0; ks < 8; ++ks) {
            uint32_t a[4];
            ldsm_x4(a, qfrag + (uint32_t)(ks * 8) * 4u);
#pragma unroll
            for (int nf = 0; nf < 8; nf += 2) {
                uint32_t b[4];
                ldsm_x4(b, kbuf + (uint32_t)((nf * 8 + krow) * KVS + ks * 8 + kcsel) * 4u);
                mma_h16(s[nf],     a, b);
                mma_h16(s[nf + 1], a, b + 2);
            }
        }

        // ---- mask only on boundary tiles ----
        if (kb == kb_hi || t0 < lo) {
            const int r0g = q0 + rb + g, r1g = r0g + 8;
#pragma unroll
            for (int nf = 0; nf < 8; ++nf) {
                int c0 = t0 + nf * 8 + 2 * tig;
                int c1 = c0 + 1;
                bool ok00 = (c0 <= r0g) && (r0g - c0 < WIN);
                bool ok01 = (c1 <= r0g) && (r0g - c1 < WIN);
                bool ok10 = (c0 <= r1g) && (r1g - c0 < WIN);
                bool ok11 = (c1 <= r1g) && (r1g - c1 < WIN);
                s[nf][0] = ok00 ? s[nf][0] : NEG;
                s[nf][1] = ok01 ? s[nf][1] : NEG;
                s[nf][2] = ok10 ? s[nf][2] : NEG;
                s[nf][3] = ok11 ? s[nf][3] : NEG;
            }
        }

        // ---- online softmax (exp2 domain), P packed to A-fragments ----
        float mt0 = NEG, mt1 = NEG;
#pragma unroll
        for (int nf = 0; nf < 8; ++nf) {
            mt0 = fmaxf(mt0, fmaxf(s[nf][0], s[nf][1]));
            mt1 = fmaxf(mt1, fmaxf(s[nf][2], s[nf][3]));
        }
        mt0 = fmaxf(mt0, __shfl_xor_sync(0xffffffffu, mt0, 1));
        mt0 = fmaxf(mt0, __shfl_xor_sync(0xffffffffu, mt0, 2));
        mt1 = fmaxf(mt1, __shfl_xor_sync(0xffffffffu, mt1, 1));
        mt1 = fmaxf(mt1, __shfl_xor_sync(0xffffffffu, mt1, 2));

        float mn0 = fmaxf(m0, mt0), mn1 = fmaxf(m1, mt1);
        float esc0 = exp2f(m0 - mn0);
        float esc1 = exp2f(m1 - mn1);

        uint32_t pa[4][4];   // PV A-fragments, kc = key-chunk of 16
        float rs0 = 0.f, rs1 = 0.f;
#pragma unroll
        for (int nf = 0; nf < 8; ++nf) {
            float p00 = exp2f(s[nf][0] - mn0);
            float p01 = exp2f(s[nf][1] - mn0);
            float p10 = exp2f(s[nf][2] - mn1);
            float p11 = exp2f(s[nf][3] - mn1);
            rs0 += p00 + p01;
            rs1 += p10 + p11;
            const int kc = nf >> 1;
            if ((nf & 1) == 0) {
                pa[kc][0] = pack2(p00, p01);   // rows g,   keys 16kc+2tig(+1)
                pa[kc][1] = pack2(p10, p11);   // rows g+8
            } else {
                pa[kc][2] = pack2(p00, p01);   // rows g,   keys 16kc+8+2tig(+1)
                pa[kc][3] = pack2(p10, p11);   // rows g+8
            }
        }
        rs0 += __shfl_xor_sync(0xffffffffu, rs0, 1);
        rs0 += __shfl_xor_sync(0xffffffffu, rs0, 2);
        rs1 += __shfl_xor_sync(0xffffffffu, rs1, 1);
        rs1 += __shfl_xor_sync(0xffffffffu, rs1, 2);

        l0 = l0 * esc0 + rs0; m0 = mn0;
        l1 = l1 * esc1 + rs1; m1 = mn1;

#pragma unroll
        for (int nf = 0; nf < 16; ++nf) {
            o[nf][0] *= esc0; o[nf][1] *= esc0;
            o[nf][2] *= esc1; o[nf][3] *= esc1;
        }

        // ---- O += P @ V (P in registers) ----
#pragma unroll
        for (int kc = 0; kc < 4; ++kc) {
#pragma unroll
            for (int nf = 0; nf < 16; nf += 2) {
                uint32_t b[4];
                ldsm_x4_t(b, vbuf + (uint32_t)((kc * 16 + arow) * KVS + (nf + vcsel) * 4) * 4u);
                mma_h16(o[nf],     pa[kc], b);
                mma_h16(o[nf + 1], pa[kc], b + 2);
            }
        }
        __syncthreads();   // all warps done with K/V before next tile overwrites
    }

    const float inv0 = 1.f / l0, inv1 = 1.f / l1;
    const int qr0 = q0 + rb + g, qr1 = qr0 + 8;
#pragma unroll
    for (int nf = 0; nf < 16; ++nf) {
        int c2 = h * (HD / 2) + nf * 4 + tig;
        outh[(size_t)qr0 * (NHQ * HD / 2) + c2] = pack2(o[nf][0] * inv0, o[nf][1] * inv0);
        outh[(size_t)qr1 * (NHQ * HD / 2) + c2] = pack2(o[nf][2] * inv1, o[nf][3] * inv1);
    }
}

// ---------------------------------------------------------------------------
extern "C" void kernel_launch(void* const* d_in, const int* in_sizes, int n_in,
                              void* d_out, int out_size) {
    const float* hs  = (const float*)d_in[0];
    const float* fc  = (const float*)d_in[1];
    const int*   pos = (const int*)d_in[4];
    const float* Wq  = (const float*)d_in[5];
    const float* Wk  = (const float*)d_in[6];
    const float* Wv  = (const float*)d_in[7];
    const float* Wo  = (const float*)d_in[8];
    float* out = (float*)d_out;

    __half *hsh;
    uint32_t *attnh, *wqp, *wkp, *wvp, *wop;
    cudaGetSymbolAddress((void**)&hsh,   g_hsh);
    cudaGetSymbolAddress((void**)&attnh, g_attnh);
    cudaGetSymbolAddress((void**)&wqp,   g_wqp);
    cudaGetSymbolAddress((void**)&wkp,   g_wkp);
    cudaGetSymbolAddress((void**)&wvp,   g_wvp);
    cudaGetSymbolAddress((void**)&wop,   g_wop);

    prep_all<<<PREP_U / 256, 256>>>(hs, Wq, Wk, Wv, Wo);

    cudaFuncSetAttribute((const void*)gemm_h<1>, cudaFuncAttributeMaxDynamicSharedMemorySize, SMEM_G);
    cudaFuncSetAttribute((const void*)gemm_h<0>, cudaFuncAttributeMaxDynamicSharedMemorySize, SMEM_G);
    cudaFuncSetAttribute((const void*)attn_h,    cudaFuncAttributeMaxDynamicSharedMemorySize, ATT_SMEM);

    // fused QKV + RoPE: 24 col blocks (16 Q + 4 K + 4 V) x 16 rows, 2 CTAs/SM
    gemm_h<1><<<dim3(24, 16), 256, SMEM_G>>>(hsh, HID, wqp, 16, wkp, 4, wvp,
                                             nullptr, 0, fc, pos);

    // attention: 64 q-rows per CTA, 4 warps, 3 CTAs/SM, register-resident P
    attn_h<<<dim3(S_LEN / 64, NHQ), 128, ATT_SMEM>>>(attnh);

    // O projection: 16x16 = 256 CTAs, 2 CTAs/SM
    gemm_h<0><<<dim3(16, 16), 256, SMEM_G>>>((const __half*)attnh, NHQ * HD, wop, 16,
                                             nullptr, 0, nullptr, out, HID, nullptr, nullptr);
}